// round 11
// baseline (speedup 1.0000x reference)
#include <cuda_runtime.h>
#include <cuda_bf16.h>
#include <cstdint>

// ---------------------------------------------------------------------------
// Attention_21474836480706: B=4, N=1024, H=16, D=72, HID=1152 (fp32)
// R11: k_gemm mainloop restructured register-lean (B frags resident, A frags
// streamed per mf) so __launch_bounds__(256,2) fits without spills.
// Flash unchanged. Math bitwise-identical to R10.
// ---------------------------------------------------------------------------

namespace {
constexpr int Bb    = 4;
constexpr int Nn    = 1024;
constexpr int Hh    = 16;
constexpr int Dd    = 72;
constexpr int DP    = 80;
constexpr int HID   = 1152;
constexpr int ATT   = Hh * Dd;        // 1152
constexpr int MTOK  = Bb * Nn;        // 4096
constexpr int QKVN  = 3 * ATT;        // 3456
constexpr int BHEAD = Bb * Hh;        // 64
}

// ------------------------------ scratch ------------------------------------
__device__ __align__(16) __nv_bfloat16 g_qh[(size_t)BHEAD * Nn * DP];   // Q pre-scaled
__device__ __align__(16) __nv_bfloat16 g_ql[(size_t)BHEAD * Nn * DP];
__device__ __align__(16) __nv_bfloat16 g_kh[(size_t)BHEAD * Nn * DP];
__device__ __align__(16) __nv_bfloat16 g_kl[(size_t)BHEAD * Nn * DP];
__device__ __align__(16) __nv_bfloat16 g_vth[(size_t)BHEAD * Dd * Nn];  // V^T [bh][d][tok]
__device__ __align__(16) __nv_bfloat16 g_vtl[(size_t)BHEAD * Dd * Nn];

__device__ __align__(16) __nv_bfloat16 g_xa_hi[(size_t)MTOK * HID];
__device__ __align__(16) __nv_bfloat16 g_xa_lo[(size_t)MTOK * HID];
__device__ __align__(16) __nv_bfloat16 g_oa_hi[(size_t)MTOK * HID];
__device__ __align__(16) __nv_bfloat16 g_oa_lo[(size_t)MTOK * HID];
__device__ __align__(16) __nv_bfloat16 g_wqkvt_hi[(size_t)QKVN * HID];
__device__ __align__(16) __nv_bfloat16 g_wqkvt_lo[(size_t)QKVN * HID];
__device__ __align__(16) __nv_bfloat16 g_wot_hi[(size_t)HID * HID];
__device__ __align__(16) __nv_bfloat16 g_wot_lo[(size_t)HID * HID];

// --------------------------- helpers ---------------------------------------
__device__ __forceinline__ uint32_t smem_u32(const void* p) {
    uint32_t a;
    asm("{ .reg .u64 t; cvta.to.shared.u64 t, %1; cvt.u32.u64 %0, t; }" : "=r"(a) : "l"(p));
    return a;
}
__device__ __forceinline__ void cp16(uint32_t s, const void* g) {
    asm volatile("cp.async.cg.shared.global [%0], [%1], 16;" :: "r"(s), "l"(g));
}
#define CP_COMMIT() asm volatile("cp.async.commit_group;" ::: "memory")
#define CP_WAIT(n)  asm volatile("cp.async.wait_group %0;" :: "n"(n) : "memory")

__device__ __forceinline__ void ldsm4(uint32_t& r0, uint32_t& r1, uint32_t& r2, uint32_t& r3,
                                      uint32_t a) {
    asm volatile("ldmatrix.sync.aligned.m8n8.x4.shared.b16 {%0,%1,%2,%3}, [%4];"
                 : "=r"(r0), "=r"(r1), "=r"(r2), "=r"(r3) : "r"(a));
}
__device__ __forceinline__ void ldsm2(uint32_t& r0, uint32_t& r1, uint32_t a) {
    asm volatile("ldmatrix.sync.aligned.m8n8.x2.shared.b16 {%0,%1}, [%2];"
                 : "=r"(r0), "=r"(r1) : "r"(a));
}
__device__ __forceinline__ void mma16816(float* d, const uint32_t* a, const uint32_t* b) {
    asm volatile(
        "mma.sync.aligned.m16n8k16.row.col.f32.bf16.bf16.f32 "
        "{%0,%1,%2,%3}, {%4,%5,%6,%7}, {%8,%9}, {%0,%1,%2,%3};"
        : "+f"(d[0]), "+f"(d[1]), "+f"(d[2]), "+f"(d[3])
        : "r"(a[0]), "r"(a[1]), "r"(a[2]), "r"(a[3]), "r"(b[0]), "r"(b[1]));
}
__device__ __forceinline__ __nv_bfloat162 hilo2(float a, float b, bool lo) {
    __nv_bfloat16 ha = __float2bfloat16(a), hb = __float2bfloat16(b);
    if (!lo) return __halves2bfloat162(ha, hb);
    return __halves2bfloat162(__float2bfloat16(a - __bfloat162float(ha)),
                              __float2bfloat16(b - __bfloat162float(hb)));
}
__device__ __forceinline__ void pack_hilo(float a, float b, uint32_t& hi, uint32_t& lo) {
    __nv_bfloat16 ha = __float2bfloat16(a), hb = __float2bfloat16(b);
    __nv_bfloat162 h2 = __halves2bfloat162(ha, hb);
    __nv_bfloat162 l2 = __halves2bfloat162(__float2bfloat16(a - __bfloat162float(ha)),
                                           __float2bfloat16(b - __bfloat162float(hb)));
    hi = *reinterpret_cast<uint32_t*>(&h2);
    lo = *reinterpret_cast<uint32_t*>(&l2);
}

// ---------------------------------------------------------------------------
__global__ __launch_bounds__(256) void k_zpad() {
    const int i = blockIdx.x * 256 + threadIdx.x;
    if (i >= BHEAD * Nn) return;
    const size_t o = (size_t)i * DP + Dd;
    const uint4 z = make_uint4(0, 0, 0, 0);
    *reinterpret_cast<uint4*>(&g_qh[o]) = z;
    *reinterpret_cast<uint4*>(&g_ql[o]) = z;
    *reinterpret_cast<uint4*>(&g_kh[o]) = z;
    *reinterpret_cast<uint4*>(&g_kl[o]) = z;
}

__global__ __launch_bounds__(256) void k_split(const float* __restrict__ in) {
    const int n4 = MTOK * HID / 4;
    int i = blockIdx.x * 256 + threadIdx.x;
    if (i >= n4) return;
    float4 v = reinterpret_cast<const float4*>(in)[i];
    reinterpret_cast<__nv_bfloat162*>(g_xa_hi)[2 * i]     = hilo2(v.x, v.y, false);
    reinterpret_cast<__nv_bfloat162*>(g_xa_hi)[2 * i + 1] = hilo2(v.z, v.w, false);
    reinterpret_cast<__nv_bfloat162*>(g_xa_lo)[2 * i]     = hilo2(v.x, v.y, true);
    reinterpret_cast<__nv_bfloat162*>(g_xa_lo)[2 * i + 1] = hilo2(v.z, v.w, true);
}

template <int NCOLS, int WHICH>
__global__ void k_tsplit(const float* __restrict__ W) {
    __shared__ float t[32][33];
    const int n0 = blockIdx.x * 32, k0 = blockIdx.y * 32;
    const int tx = threadIdx.x, ty = threadIdx.y;   // (32, 8)
#pragma unroll
    for (int i = 0; i < 4; ++i)
        t[ty * 4 + i][tx] = W[(size_t)(k0 + ty * 4 + i) * NCOLS + n0 + tx];
    __syncthreads();
    __nv_bfloat16* Hi = WHICH ? g_wot_hi : g_wqkvt_hi;
    __nv_bfloat16* Lo = WHICH ? g_wot_lo : g_wqkvt_lo;
#pragma unroll
    for (int i = 0; i < 4; ++i) {
        float v = t[tx][ty * 4 + i];
        __nv_bfloat16 h = __float2bfloat16(v);
        __nv_bfloat16 l = __float2bfloat16(v - __bfloat162float(h));
        size_t o = (size_t)(n0 + ty * 4 + i) * HID + k0 + tx;
        Hi[o] = h;
        Lo[o] = l;
    }
}

// ---------------------------------------------------------------------------
// HMMA GEMM (projections), 2-stage cp.async + ldmatrix, 2 CTAs/SM.
// Register-lean mainloop: B frags (hi+lo) resident, A frags streamed per mf.
// ---------------------------------------------------------------------------
namespace {
constexpr int GBM = 128, GBK = 32, GLDS = 40;
constexpr int GTILE = GBM * GLDS;
constexpr int GSTAGE = 4 * GTILE;
constexpr int GEMM_SMEM = 2 * GSTAGE * 2;         // 81920 B
}

template <int MODE>
__global__ __launch_bounds__(256, 2) void k_gemm(const float* __restrict__ bias,
                                                 float* __restrict__ Cout) {
    extern __shared__ __nv_bfloat16 gsm[];

    const int tid  = threadIdx.x;
    const int warp = tid >> 5, lane = tid & 31;
    const int wm = (warp >> 2) * 64;
    const int wn = (warp & 3) * 32;
    const int gi  = lane >> 2;
    const int tig = lane & 3;
    const int m0 = blockIdx.y * GBM;
    const int n0 = blockIdx.x * GBM;

    const int lane7 = lane & 7;
    const int aRow = lane7 + ((lane & 8) ? 8 : 0);
    const int aK   = (lane & 16) ? 8 : 0;
    const int bRow = lane7 + ((lane & 16) ? 8 : 0);
    const int bK   = (lane & 8) ? 8 : 0;

    const __nv_bfloat16* __restrict__ Ah = MODE ? g_oa_hi : g_xa_hi;
    const __nv_bfloat16* __restrict__ Al = MODE ? g_oa_lo : g_xa_lo;
    const __nv_bfloat16* __restrict__ Bh = MODE ? g_wot_hi : g_wqkvt_hi;
    const __nv_bfloat16* __restrict__ Bl = MODE ? g_wot_lo : g_wqkvt_lo;

    const int r0c = tid >> 2, k0c = (tid & 3);
    const int r1c = (tid + 256) >> 2, k1c = (tid & 3);

    auto issue_tile = [&](int kt, int stage) {
        __nv_bfloat16* base = gsm + stage * GSTAGE;
        const int kk = kt * GBK;
#pragma unroll
        for (int c = 0; c < 2; ++c) {
            const int row = c ? r1c : r0c;
            const int kc  = c ? k1c : k0c;
            const uint32_t soff = smem_u32(base + row * GLDS + kc * 8);
            const size_t ga = (size_t)(m0 + row) * HID + kk + kc * 8;
            const size_t gb = (size_t)(n0 + row) * HID + kk + kc * 8;
            cp16(soff,                 Ah + ga);
            cp16(soff + GTILE * 2,     Al + ga);
            cp16(soff + 2 * GTILE * 2, Bh + gb);
            cp16(soff + 3 * GTILE * 2, Bl + gb);
        }
        CP_COMMIT();
    };

    float acc[4][4][4] = {};
    constexpr int NT = HID / GBK;   // 36

    issue_tile(0, 0);

    for (int t = 0; t < NT; ++t) {
        if (t + 1 < NT) {
            issue_tile(t + 1, (t + 1) & 1);
            CP_WAIT(1);
        } else {
            CP_WAIT(0);
        }
        __syncthreads();

        const uint32_t uAh = smem_u32(gsm + (t & 1) * GSTAGE);
        const uint32_t uAl = uAh + GTILE * 2;
        const uint32_t uBh = uAh + 2 * GTILE * 2;
        const uint32_t uBl = uAh + 3 * GTILE * 2;

#pragma unroll
        for (int ks = 0; ks < GBK; ks += 16) {
            // B fragments resident: hi + lo (16 regs)
            uint32_t bh_[4][2], bl_[4][2];
#pragma unroll
            for (int np = 0; np < 2; ++np) {
                const uint32_t off = ((wn + np * 16 + bRow) * GLDS + ks + bK) * 2;
                ldsm4(bh_[2 * np][0], bh_[2 * np][1], bh_[2 * np + 1][0], bh_[2 * np + 1][1],
                      uBh + off);
                ldsm4(bl_[2 * np][0], bl_[2 * np][1], bl_[2 * np + 1][0], bl_[2 * np + 1][1],
                      uBl + off);
            }
            // A fragments streamed per mf (8 regs live)
#pragma unroll
            for (int mf = 0; mf < 4; ++mf) {
                uint32_t ah[4], al[4];
                const uint32_t off = ((wm + mf * 16 + aRow) * GLDS + ks + aK) * 2;
                ldsm4(ah[0], ah[1], ah[2], ah[3], uAh + off);
                ldsm4(al[0], al[1], al[2], al[3], uAl + off);
#pragma unroll
                for (int nf = 0; nf < 4; ++nf) {
                    mma16816(acc[mf][nf], ah, bh_[nf]);
                    mma16816(acc[mf][nf], al, bh_[nf]);
                    mma16816(acc[mf][nf], ah, bl_[nf]);
                }
            }
        }
        __syncthreads();
    }

    const float qscale = 0.11785113019775793f;  // 1/sqrt(72)
#pragma unroll
    for (int mf = 0; mf < 4; ++mf) {
#pragma unroll
        for (int nf = 0; nf < 4; ++nf) {
            const int row = m0 + wm + mf * 16 + gi;
            const int col = n0 + wn + nf * 8 + tig * 2;
            const float b0 = bias[col], b1 = bias[col + 1];
            float x0 = acc[mf][nf][0] + b0, y0 = acc[mf][nf][1] + b1;
            float x1 = acc[mf][nf][2] + b0, y1 = acc[mf][nf][3] + b1;
            if (MODE == 0) {
                const int which = n0 / ATT;
                const int rem = col - which * ATT;
                const int h = rem / Dd, d = rem - h * Dd;
                const int bb = row >> 10, tok = row & 1023;
                const int bh = bb * Hh + h;
                if (which < 2) {
                    if (which == 0) { x0 *= qscale; y0 *= qscale; x1 *= qscale; y1 *= qscale; }
                    __nv_bfloat16* Hi = which ? g_kh : g_qh;
                    __nv_bfloat16* Lo = which ? g_kl : g_ql;
                    const size_t o0 = ((size_t)bh * Nn + tok) * DP + d;
                    const size_t o1 = o0 + 8 * DP;
                    *reinterpret_cast<__nv_bfloat162*>(&Hi[o0]) = hilo2(x0, y0, false);
                    *reinterpret_cast<__nv_bfloat162*>(&Lo[o0]) = hilo2(x0, y0, true);
                    *reinterpret_cast<__nv_bfloat162*>(&Hi[o1]) = hilo2(x1, y1, false);
                    *reinterpret_cast<__nv_bfloat162*>(&Lo[o1]) = hilo2(x1, y1, true);
                } else {
                    const size_t b0o = ((size_t)bh * Dd + d) * Nn + tok;
                    const size_t b1o = b0o + Nn;
                    __nv_bfloat16 h0 = __float2bfloat16(x0);
                    __nv_bfloat16 h1 = __float2bfloat16(y0);
                    __nv_bfloat16 h2 = __float2bfloat16(x1);
                    __nv_bfloat16 h3 = __float2bfloat16(y1);
                    g_vth[b0o]     = h0;
                    g_vth[b1o]     = h1;
                    g_vth[b0o + 8] = h2;
                    g_vth[b1o + 8] = h3;
                    g_vtl[b0o]     = __float2bfloat16(x0 - __bfloat162float(h0));
                    g_vtl[b1o]     = __float2bfloat16(y0 - __bfloat162float(h1));
                    g_vtl[b0o + 8] = __float2bfloat16(x1 - __bfloat162float(h2));
                    g_vtl[b1o + 8] = __float2bfloat16(y1 - __bfloat162float(h3));
                }
            } else {
                *reinterpret_cast<float2*>(&Cout[(size_t)row * HID + col]) = make_float2(x0, y0);
                *reinterpret_cast<float2*>(&Cout[(size_t)(row + 8) * HID + col]) = make_float2(x1, y1);
            }
        }
    }
}

// ---------------------------------------------------------------------------
// Flash attention (unchanged from R9): 64-token K/V tiles, 2 CTAs/SM,
// exp/pack/PV interleaved per k-chunk.
// ---------------------------------------------------------------------------
namespace {
constexpr int LDSK  = 88;
constexpr int LDSV  = 72;
constexpr int KROWS = 64;
constexpr int QELE  = 128 * LDSK;
constexpr int KELE  = KROWS * LDSK;
constexpr int VELE  = Dd * LDSV;
constexpr int FLASH_SMEM = (2 * QELE + 2 * KELE + 2 * VELE) * 2;   // 88320 B
}

__global__ __launch_bounds__(256, 2) void k_flash() {
    extern __shared__ __nv_bfloat16 sm[];
    __nv_bfloat16* sQh = sm;
    __nv_bfloat16* sQl = sm + QELE;
    __nv_bfloat16* sKh = sm + 2 * QELE;
    __nv_bfloat16* sKl = sm + 2 * QELE + KELE;
    __nv_bfloat16* sVh = sm + 2 * QELE + 2 * KELE;
    __nv_bfloat16* sVl = sm + 2 * QELE + 2 * KELE + VELE;

    const int tid  = threadIdx.x;
    const int warp = tid >> 5, lane = tid & 31;
    const int wm  = warp * 16;
    const int gi  = lane >> 2;
    const int tig = lane & 3;
    const int bh = blockIdx.y;
    const int m0 = blockIdx.x * 128;

    const int lane7 = lane & 7;
    const int aRow = lane7 + ((lane & 8) ? 8 : 0);
    const int aK   = (lane & 16) ? 8 : 0;
    const int bRow = lane7 + ((lane & 16) ? 8 : 0);
    const int bK   = (lane & 8) ? 8 : 0;

    const uint32_t uQh = smem_u32(sQh), uQl = smem_u32(sQl);
    const uint32_t uKh = smem_u32(sKh), uKl = smem_u32(sKl);
    const uint32_t uVh = smem_u32(sVh), uVl = smem_u32(sVl);

    const __nv_bfloat16* __restrict__ Qh = g_qh + (size_t)bh * Nn * DP;
    const __nv_bfloat16* __restrict__ Ql = g_ql + (size_t)bh * Nn * DP;
    const __nv_bfloat16* __restrict__ Kh = g_kh + (size_t)bh * Nn * DP;
    const __nv_bfloat16* __restrict__ Kl = g_kl + (size_t)bh * Nn * DP;
    const __nv_bfloat16* __restrict__ Vh = g_vth + (size_t)bh * Dd * Nn;
    const __nv_bfloat16* __restrict__ Vl = g_vtl + (size_t)bh * Dd * Nn;

    auto issueK = [&](int kt) {
        const int nn = kt * KROWS;
#pragma unroll
        for (int c = 0; c < 3; ++c) {
            const int chunk = tid + c * 256;
            if (chunk < KROWS * 10) {
                const int row = chunk / 10;
                const int kc  = chunk - row * 10;
                const size_t gk = (size_t)(nn + row) * DP + kc * 8;
                cp16(smem_u32(sKh + row * LDSK + kc * 8), Kh + gk);
                cp16(smem_u32(sKl + row * LDSK + kc * 8), Kl + gk);
            }
        }
        CP_COMMIT();
    };
    auto issueV = [&](int kt) {
        const int nn = kt * KROWS;
#pragma unroll
        for (int c = 0; c < 3; ++c) {
            const int chunk = tid + c * 256;
            if (chunk < Dd * 8) {
                const int row = chunk >> 3;
                const int kc  = chunk & 7;
                const size_t gv = (size_t)row * Nn + nn + kc * 8;
                cp16(smem_u32(sVh + row * LDSV + kc * 8), Vh + gv);
                cp16(smem_u32(sVl + row * LDSV + kc * 8), Vl + gv);
            }
        }
        CP_COMMIT();
    };

    issueK(0);
#pragma unroll
    for (int c = 0; c < 5; ++c) {
        const int chunk = tid + c * 256;
        const int row = chunk / 10;
        const int kc  = chunk - row * 10;
        const int soff = row * LDSK + kc * 8;
        const size_t gq = (size_t)(m0 + row) * DP + kc * 8;
        *reinterpret_cast<uint4*>(&sQh[soff]) = *reinterpret_cast<const uint4*>(&Qh[gq]);
        *reinterpret_cast<uint4*>(&sQl[soff]) = *reinterpret_cast<const uint4*>(&Ql[gq]);
    }

    float m_run0 = -3.4e38f, m_run1 = -3.4e38f;
    float l_run0 = 0.f, l_run1 = 0.f;
    float o[9][4] = {};

    for (int kt = 0; kt < Nn / KROWS; ++kt) {
        CP_WAIT(0);
        __syncthreads();

        issueV(kt);

        float s[8][4];
#pragma unroll
        for (int nf = 0; nf < 8; ++nf)
            s[nf][0] = s[nf][1] = s[nf][2] = s[nf][3] = 0.f;
#pragma unroll
        for (int ks = 0; ks < DP; ks += 16) {
            uint32_t aH[4], aL[4], b[2][2];
            const uint32_t aoff = ((wm + aRow) * LDSK + ks + aK) * 2;
            ldsm4(aH[0], aH[1], aH[2], aH[3], uQh + aoff);
            ldsm4(aL[0], aL[1], aL[2], aL[3], uQl + aoff);
#pragma unroll
            for (int np = 0; np < 4; ++np) {
                const uint32_t boff = ((np * 16 + bRow) * LDSK + ks + bK) * 2;
                ldsm4(b[0][0], b[0][1], b[1][0], b[1][1], uKh + boff);
                mma16816(s[2 * np],     aH, b[0]);
                mma16816(s[2 * np],     aL, b[0]);
                mma16816(s[2 * np + 1], aH, b[1]);
                mma16816(s[2 * np + 1], aL, b[1]);
            }
#pragma unroll
            for (int np = 0; np < 4; ++np) {
                const uint32_t boff = ((np * 16 + bRow) * LDSK + ks + bK) * 2;
                ldsm4(b[0][0], b[0][1], b[1][0], b[1][1], uKl + boff);
                mma16816(s[2 * np],     aH, b[0]);
                mma16816(s[2 * np + 1], aH, b[1]);
            }
        }

        float mt0 = -3.4e38f, mt1 = -3.4e38f;
#pragma unroll
        for (int nf = 0; nf < 8; ++nf) {
            mt0 = fmaxf(mt0, fmaxf(s[nf][0], s[nf][1]));
            mt1 = fmaxf(mt1, fmaxf(s[nf][2], s[nf][3]));
        }
        mt0 = fmaxf(mt0, __shfl_xor_sync(0xffffffffu, mt0, 1));
        mt0 = fmaxf(mt0, __shfl_xor_sync(0xffffffffu, mt0, 2));
        mt1 = fmaxf(mt1, __shfl_xor_sync(0xffffffffu, mt1, 1));
        mt1 = fmaxf(mt1, __shfl_xor_sync(0xffffffffu, mt1, 2));
        const float mn0 = fmaxf(m_run0, mt0);
        const float mn1 = fmaxf(m_run1, mt1);
        const float sc0 = __expf(m_run0 - mn0);
        const float sc1 = __expf(m_run1 - mn1);
        m_run0 = mn0;
        m_run1 = mn1;
#pragma unroll
        for (int nf = 0; nf < 9; ++nf) {
            o[nf][0] *= sc0; o[nf][1] *= sc0;
            o[nf][2] *= sc1; o[nf][3] *= sc1;
        }

        CP_WAIT(0);
        __syncthreads();

        if (kt + 1 < Nn / KROWS) issueK(kt + 1);

        float ps0 = 0.f, ps1 = 0.f;
#pragma unroll
        for (int kc = 0; kc < 4; ++kc) {
            const int nf0 = 2 * kc, nf1 = 2 * kc + 1;
            const float p00 = __expf(s[nf0][0] - mn0), p01 = __expf(s[nf0][1] - mn0);
            const float p02 = __expf(s[nf0][2] - mn1), p03 = __expf(s[nf0][3] - mn1);
            const float p10 = __expf(s[nf1][0] - mn0), p11 = __expf(s[nf1][1] - mn0);
            const float p12 = __expf(s[nf1][2] - mn1), p13 = __expf(s[nf1][3] - mn1);
            ps0 += p00 + p01 + p10 + p11;
            ps1 += p02 + p03 + p12 + p13;
            uint32_t pH[4], pL[4];
            pack_hilo(p00, p01, pH[0], pL[0]);
            pack_hilo(p02, p03, pH[1], pL[1]);
            pack_hilo(p10, p11, pH[2], pL[2]);
            pack_hilo(p12, p13, pH[3], pL[3]);

            uint32_t b[9][2];
#pragma unroll
            for (int np = 0; np < 4; ++np) {
                const uint32_t off = ((np * 16 + bRow) * LDSV + kc * 16 + bK) * 2;
                ldsm4(b[2 * np][0], b[2 * np][1], b[2 * np + 1][0], b[2 * np + 1][1], uVh + off);
            }
            {
                const uint32_t off = ((64 + lane7) * LDSV + kc * 16 + bK) * 2;
                ldsm2(b[8][0], b[8][1], uVh + off);
            }
#pragma unroll
            for (int nf = 0; nf < 9; ++nf) {
                mma16816(o[nf], pH, b[nf]);
                mma16816(o[nf], pL, b[nf]);
            }
#pragma unroll
            for (int np = 0; np < 4; ++np) {
                const uint32_t off = ((np * 16 + bRow) * LDSV + kc * 16 + bK) * 2;
                ldsm4(b[2 * np][0], b[2 * np][1], b[2 * np + 1][0], b[2 * np + 1][1], uVl + off);
            }
            {
                const uint32_t off = ((64 + lane7) * LDSV + kc * 16 + bK) * 2;
                ldsm2(b[8][0], b[8][1], uVl + off);
            }
#pragma unroll
            for (int nf = 0; nf < 9; ++nf)
                mma16816(o[nf], pH, b[nf]);
        }
        ps0 += __shfl_xor_sync(0xffffffffu, ps0, 1);
        ps0 += __shfl_xor_sync(0xffffffffu, ps0, 2);
        ps1 += __shfl_xor_sync(0xffffffffu, ps1, 1);
        ps1 += __shfl_xor_sync(0xffffffffu, ps1, 2);
        l_run0 = l_run0 * sc0 + ps0;
        l_run1 = l_run1 * sc1 + ps1;
    }

    const float inv0 = 1.0f / l_run0;
    const float inv1 = 1.0f / l_run1;
    const int b = bh >> 4;
    const int h = bh & 15;
    const int tok0 = m0 + wm + gi;
#pragma unroll
    for (int nf = 0; nf < 9; ++nf) {
        const int col = nf * 8 + tig * 2;
        const size_t o0 = ((size_t)(b * Nn + tok0)) * HID + h * Dd + col;
        const size_t o1 = ((size_t)(b * Nn + tok0 + 8)) * HID + h * Dd + col;
        const float x0 = o[nf][0] * inv0, y0 = o[nf][1] * inv0;
        const float x1 = o[nf][2] * inv1, y1 = o[nf][3] * inv1;
        *reinterpret_cast<__nv_bfloat162*>(&g_oa_hi[o0]) = hilo2(x0, y0, false);
        *reinterpret_cast<__nv_bfloat162*>(&g_oa_lo[o0]) = hilo2(x0, y0, true);
        *reinterpret_cast<__nv_bfloat162*>(&g_oa_hi[o1]) = hilo2(x1, y1, false);
        *reinterpret_cast<__nv_bfloat162*>(&g_oa_lo[o1]) = hilo2(x1, y1, true);
    }
}

// ---------------------------------------------------------------------------
extern "C" void kernel_launch(void* const* d_in, const int* in_sizes, int n_in,
                              void* d_out, int out_size) {
    const float* x     = (const float*)d_in[0];
    const float* w_qkv = (const float*)d_in[1];
    const float* b_qkv = (const float*)d_in[2];
    const float* w_out = (const float*)d_in[3];
    const float* b_out = (const float*)d_in[4];
    float* out = (float*)d_out;

    cudaFuncSetAttribute(k_flash, cudaFuncAttributeMaxDynamicSharedMemorySize, FLASH_SMEM);
    cudaFuncSetAttribute(k_gemm<0>, cudaFuncAttributeMaxDynamicSharedMemorySize, GEMM_SMEM);
    cudaFuncSetAttribute(k_gemm<1>, cudaFuncAttributeMaxDynamicSharedMemorySize, GEMM_SMEM);

    const int n4 = MTOK * HID / 4;

    // prep
    k_zpad<<<(BHEAD * Nn + 255) / 256, 256>>>();
    k_split<<<(n4 + 255) / 256, 256>>>(x);
    k_tsplit<QKVN, 0><<<dim3(QKVN / 32, HID / 32), dim3(32, 8)>>>(w_qkv);
    k_tsplit<HID, 1><<<dim3(HID / 32, HID / 32), dim3(32, 8)>>>(w_out);

    // 1. QKV projection -> Q(scaled)/K hi/lo (padded), V^T hi/lo
    k_gemm<0><<<dim3(QKVN / 128, MTOK / 128), 256, GEMM_SMEM>>>(b_qkv, nullptr);

    // 2. fused flash attention -> g_oa hi/lo
    k_flash<<<dim3(Nn / 128, BHEAD), 256, FLASH_SMEM>>>();

    // 3. output projection
    k_gemm<1><<<dim3(HID / 128, MTOK / 128), 256, GEMM_SMEM>>>(b_out, out);
}

// round 12
// speedup vs baseline: 1.3991x; 1.3991x over previous
#include <cuda_runtime.h>
#include <cuda_fp16.h>
#include <cstdint>

// ---------------------------------------------------------------------------
// Attention_21474836480706: B=4, N=1024, H=16, D=72, HID=1152 (fp32)
// R12: fp16 asymmetric 2-pass replaces bf16 3-pass. Left operands (x, Q, P,
// attn-out) split hi/lo fp16; right operands (W, K, V) single fp16.
// 2 MMA passes per unit -> 2/3 the tensor work, smaller smem/prep.
// ---------------------------------------------------------------------------

namespace {
constexpr int Bb    = 4;
constexpr int Nn    = 1024;
constexpr int Hh    = 16;
constexpr int Dd    = 72;
constexpr int DP    = 80;
constexpr int HID   = 1152;
constexpr int ATT   = Hh * Dd;        // 1152
constexpr int MTOK  = Bb * Nn;        // 4096
constexpr int QKVN  = 3 * ATT;        // 3456
constexpr int BHEAD = Bb * Hh;        // 64
}

// ------------------------------ scratch ------------------------------------
__device__ __align__(16) __half g_qh[(size_t)BHEAD * Nn * DP];   // Q hi (pre-scaled)
__device__ __align__(16) __half g_ql[(size_t)BHEAD * Nn * DP];   // Q lo
__device__ __align__(16) __half g_kh[(size_t)BHEAD * Nn * DP];   // K (single fp16)
__device__ __align__(16) __half g_vth[(size_t)BHEAD * Dd * Nn];  // V^T (single fp16)

__device__ __align__(16) __half g_xa_hi[(size_t)MTOK * HID];
__device__ __align__(16) __half g_xa_lo[(size_t)MTOK * HID];
__device__ __align__(16) __half g_oa_hi[(size_t)MTOK * HID];
__device__ __align__(16) __half g_oa_lo[(size_t)MTOK * HID];
__device__ __align__(16) __half g_wqkvt[(size_t)QKVN * HID];     // W_qkv^T (single fp16)
__device__ __align__(16) __half g_wot[(size_t)HID * HID];        // W_out^T (single fp16)

// --------------------------- helpers ---------------------------------------
__device__ __forceinline__ uint32_t smem_u32(const void* p) {
    uint32_t a;
    asm("{ .reg .u64 t; cvta.to.shared.u64 t, %1; cvt.u32.u64 %0, t; }" : "=r"(a) : "l"(p));
    return a;
}
__device__ __forceinline__ void cp16(uint32_t s, const void* g) {
    asm volatile("cp.async.cg.shared.global [%0], [%1], 16;" :: "r"(s), "l"(g));
}
#define CP_COMMIT() asm volatile("cp.async.commit_group;" ::: "memory")
#define CP_WAIT(n)  asm volatile("cp.async.wait_group %0;" :: "n"(n) : "memory")

__device__ __forceinline__ void ldsm4(uint32_t& r0, uint32_t& r1, uint32_t& r2, uint32_t& r3,
                                      uint32_t a) {
    asm volatile("ldmatrix.sync.aligned.m8n8.x4.shared.b16 {%0,%1,%2,%3}, [%4];"
                 : "=r"(r0), "=r"(r1), "=r"(r2), "=r"(r3) : "r"(a));
}
__device__ __forceinline__ void ldsm2(uint32_t& r0, uint32_t& r1, uint32_t a) {
    asm volatile("ldmatrix.sync.aligned.m8n8.x2.shared.b16 {%0,%1}, [%2];"
                 : "=r"(r0), "=r"(r1) : "r"(a));
}
__device__ __forceinline__ void mma16816(float* d, const uint32_t* a, const uint32_t* b) {
    asm volatile(
        "mma.sync.aligned.m16n8k16.row.col.f32.f16.f16.f32 "
        "{%0,%1,%2,%3}, {%4,%5,%6,%7}, {%8,%9}, {%0,%1,%2,%3};"
        : "+f"(d[0]), "+f"(d[1]), "+f"(d[2]), "+f"(d[3])
        : "r"(a[0]), "r"(a[1]), "r"(a[2]), "r"(a[3]), "r"(b[0]), "r"(b[1]));
}
__device__ __forceinline__ __half2 hilo2(float a, float b, bool lo) {
    __half ha = __float2half(a), hb = __float2half(b);
    if (!lo) return __halves2half2(ha, hb);
    return __halves2half2(__float2half(a - __half2float(ha)),
                          __float2half(b - __half2float(hb)));
}
__device__ __forceinline__ void pack_hilo(float a, float b, uint32_t& hi, uint32_t& lo) {
    __half ha = __float2half(a), hb = __float2half(b);
    __half2 h2 = __halves2half2(ha, hb);
    __half2 l2 = __halves2half2(__float2half(a - __half2float(ha)),
                                __float2half(b - __half2float(hb)));
    hi = *reinterpret_cast<uint32_t*>(&h2);
    lo = *reinterpret_cast<uint32_t*>(&l2);
}

// ---------------------------------------------------------------------------
__global__ __launch_bounds__(256) void k_zpad() {
    const int i = blockIdx.x * 256 + threadIdx.x;
    if (i >= BHEAD * Nn) return;
    const size_t o = (size_t)i * DP + Dd;
    const uint4 z = make_uint4(0, 0, 0, 0);
    *reinterpret_cast<uint4*>(&g_qh[o]) = z;
    *reinterpret_cast<uint4*>(&g_ql[o]) = z;
    *reinterpret_cast<uint4*>(&g_kh[o]) = z;
}

__global__ __launch_bounds__(256) void k_split(const float* __restrict__ in) {
    const int n4 = MTOK * HID / 4;
    int i = blockIdx.x * 256 + threadIdx.x;
    if (i >= n4) return;
    float4 v = reinterpret_cast<const float4*>(in)[i];
    reinterpret_cast<__half2*>(g_xa_hi)[2 * i]     = hilo2(v.x, v.y, false);
    reinterpret_cast<__half2*>(g_xa_hi)[2 * i + 1] = hilo2(v.z, v.w, false);
    reinterpret_cast<__half2*>(g_xa_lo)[2 * i]     = hilo2(v.x, v.y, true);
    reinterpret_cast<__half2*>(g_xa_lo)[2 * i + 1] = hilo2(v.z, v.w, true);
}

// transpose: W[K][NCOLS] fp32 -> Wt [NCOLS][K=1152] single fp16
template <int NCOLS, int WHICH>
__global__ void k_tsplit(const float* __restrict__ W) {
    __shared__ float t[32][33];
    const int n0 = blockIdx.x * 32, k0 = blockIdx.y * 32;
    const int tx = threadIdx.x, ty = threadIdx.y;   // (32, 8)
#pragma unroll
    for (int i = 0; i < 4; ++i)
        t[ty * 4 + i][tx] = W[(size_t)(k0 + ty * 4 + i) * NCOLS + n0 + tx];
    __syncthreads();
    __half* Hi = WHICH ? g_wot : g_wqkvt;
#pragma unroll
    for (int i = 0; i < 4; ++i) {
        float v = t[tx][ty * 4 + i];
        Hi[(size_t)(n0 + ty * 4 + i) * HID + k0 + tx] = __float2half(v);
    }
}

// ---------------------------------------------------------------------------
// HMMA GEMM (projections): fp16 2-pass. smem per stage: Ah, Al, Bh (3 tiles).
// ---------------------------------------------------------------------------
namespace {
constexpr int GBM = 128, GBK = 32, GLDS = 40;
constexpr int GTILE = GBM * GLDS;
constexpr int GSTAGE = 3 * GTILE;
constexpr int GEMM_SMEM = 2 * GSTAGE * 2;         // 61440 B
}

template <int MODE>
__global__ __launch_bounds__(256, 2) void k_gemm(const float* __restrict__ bias,
                                                 float* __restrict__ Cout) {
    extern __shared__ __half gsm[];

    const int tid  = threadIdx.x;
    const int warp = tid >> 5, lane = tid & 31;
    const int wm = (warp >> 2) * 64;
    const int wn = (warp & 3) * 32;
    const int gi  = lane >> 2;
    const int tig = lane & 3;
    const int m0 = blockIdx.y * GBM;
    const int n0 = blockIdx.x * GBM;

    const int lane7 = lane & 7;
    const int aRow = lane7 + ((lane & 8) ? 8 : 0);
    const int aK   = (lane & 16) ? 8 : 0;
    const int bRow = lane7 + ((lane & 16) ? 8 : 0);
    const int bK   = (lane & 8) ? 8 : 0;

    const __half* __restrict__ Ah = MODE ? g_oa_hi : g_xa_hi;
    const __half* __restrict__ Al = MODE ? g_oa_lo : g_xa_lo;
    const __half* __restrict__ Bh = MODE ? g_wot : g_wqkvt;

    const int r0c = tid >> 2, k0c = (tid & 3);
    const int r1c = (tid + 256) >> 2, k1c = (tid & 3);

    auto issue_tile = [&](int kt, int stage) {
        __half* base = gsm + stage * GSTAGE;
        const int kk = kt * GBK;
#pragma unroll
        for (int c = 0; c < 2; ++c) {
            const int row = c ? r1c : r0c;
            const int kc  = c ? k1c : k0c;
            const uint32_t soff = smem_u32(base + row * GLDS + kc * 8);
            const size_t ga = (size_t)(m0 + row) * HID + kk + kc * 8;
            const size_t gb = (size_t)(n0 + row) * HID + kk + kc * 8;
            cp16(soff,                 Ah + ga);
            cp16(soff + GTILE * 2,     Al + ga);
            cp16(soff + 2 * GTILE * 2, Bh + gb);
        }
        CP_COMMIT();
    };

    float acc[4][4][4] = {};
    constexpr int NT = HID / GBK;   // 36

    issue_tile(0, 0);

    for (int t = 0; t < NT; ++t) {
        if (t + 1 < NT) {
            issue_tile(t + 1, (t + 1) & 1);
            CP_WAIT(1);
        } else {
            CP_WAIT(0);
        }
        __syncthreads();

        const uint32_t uAh = smem_u32(gsm + (t & 1) * GSTAGE);
        const uint32_t uAl = uAh + GTILE * 2;
        const uint32_t uBh = uAh + 2 * GTILE * 2;

#pragma unroll
        for (int ks = 0; ks < GBK; ks += 16) {
            uint32_t b[4][2];
#pragma unroll
            for (int np = 0; np < 2; ++np) {
                const uint32_t off = ((wn + np * 16 + bRow) * GLDS + ks + bK) * 2;
                ldsm4(b[2 * np][0], b[2 * np][1], b[2 * np + 1][0], b[2 * np + 1][1],
                      uBh + off);
            }
#pragma unroll
            for (int mf = 0; mf < 4; ++mf) {
                uint32_t ah[4], al[4];
                const uint32_t off = ((wm + mf * 16 + aRow) * GLDS + ks + aK) * 2;
                ldsm4(ah[0], ah[1], ah[2], ah[3], uAh + off);
                ldsm4(al[0], al[1], al[2], al[3], uAl + off);
#pragma unroll
                for (int nf = 0; nf < 4; ++nf) {
                    mma16816(acc[mf][nf], ah, b[nf]);
                    mma16816(acc[mf][nf], al, b[nf]);
                }
            }
        }
        __syncthreads();
    }

    const float qscale = 0.11785113019775793f;  // 1/sqrt(72)
#pragma unroll
    for (int mf = 0; mf < 4; ++mf) {
#pragma unroll
        for (int nf = 0; nf < 4; ++nf) {
            const int row = m0 + wm + mf * 16 + gi;
            const int col = n0 + wn + nf * 8 + tig * 2;
            const float b0 = bias[col], b1 = bias[col + 1];
            float x0 = acc[mf][nf][0] + b0, y0 = acc[mf][nf][1] + b1;
            float x1 = acc[mf][nf][2] + b0, y1 = acc[mf][nf][3] + b1;
            if (MODE == 0) {
                const int which = n0 / ATT;
                const int rem = col - which * ATT;
                const int h = rem / Dd, d = rem - h * Dd;
                const int bb = row >> 10, tok = row & 1023;
                const int bh = bb * Hh + h;
                if (which == 0) {
                    x0 *= qscale; y0 *= qscale; x1 *= qscale; y1 *= qscale;
                    const size_t o0 = ((size_t)bh * Nn + tok) * DP + d;
                    const size_t o1 = o0 + 8 * DP;
                    *reinterpret_cast<__half2*>(&g_qh[o0]) = hilo2(x0, y0, false);
                    *reinterpret_cast<__half2*>(&g_ql[o0]) = hilo2(x0, y0, true);
                    *reinterpret_cast<__half2*>(&g_qh[o1]) = hilo2(x1, y1, false);
                    *reinterpret_cast<__half2*>(&g_ql[o1]) = hilo2(x1, y1, true);
                } else if (which == 1) {
                    const size_t o0 = ((size_t)bh * Nn + tok) * DP + d;
                    const size_t o1 = o0 + 8 * DP;
                    *reinterpret_cast<__half2*>(&g_kh[o0]) = hilo2(x0, y0, false);
                    *reinterpret_cast<__half2*>(&g_kh[o1]) = hilo2(x1, y1, false);
                } else {
                    const size_t b0o = ((size_t)bh * Dd + d) * Nn + tok;
                    const size_t b1o = b0o + Nn;
                    g_vth[b0o]     = __float2half(x0);
                    g_vth[b1o]     = __float2half(y0);
                    g_vth[b0o + 8] = __float2half(x1);
                    g_vth[b1o + 8] = __float2half(y1);
                }
            } else {
                *reinterpret_cast<float2*>(&Cout[(size_t)row * HID + col]) = make_float2(x0, y0);
                *reinterpret_cast<float2*>(&Cout[(size_t)(row + 8) * HID + col]) = make_float2(x1, y1);
            }
        }
    }
}

// ---------------------------------------------------------------------------
// Flash attention: fp16 2-pass. smem: Qh, Ql, Kh, Vh (66.7 KB), 2 CTAs/SM.
// ---------------------------------------------------------------------------
namespace {
constexpr int LDSK  = 88;
constexpr int LDSV  = 72;
constexpr int KROWS = 64;
constexpr int QELE  = 128 * LDSK;
constexpr int KELE  = KROWS * LDSK;
constexpr int VELE  = Dd * LDSV;
constexpr int FLASH_SMEM = (2 * QELE + KELE + VELE) * 2;   // 66688 B
}

__global__ __launch_bounds__(256, 2) void k_flash() {
    extern __shared__ __half sm[];
    __half* sQh = sm;
    __half* sQl = sm + QELE;
    __half* sKh = sm + 2 * QELE;
    __half* sVh = sm + 2 * QELE + KELE;

    const int tid  = threadIdx.x;
    const int warp = tid >> 5, lane = tid & 31;
    const int wm  = warp * 16;
    const int gi  = lane >> 2;
    const int tig = lane & 3;
    const int bh = blockIdx.y;
    const int m0 = blockIdx.x * 128;

    const int lane7 = lane & 7;
    const int aRow = lane7 + ((lane & 8) ? 8 : 0);
    const int aK   = (lane & 16) ? 8 : 0;
    const int bRow = lane7 + ((lane & 16) ? 8 : 0);
    const int bK   = (lane & 8) ? 8 : 0;

    const uint32_t uQh = smem_u32(sQh), uQl = smem_u32(sQl);
    const uint32_t uKh = smem_u32(sKh);
    const uint32_t uVh = smem_u32(sVh);

    const __half* __restrict__ Qh = g_qh + (size_t)bh * Nn * DP;
    const __half* __restrict__ Ql = g_ql + (size_t)bh * Nn * DP;
    const __half* __restrict__ Kh = g_kh + (size_t)bh * Nn * DP;
    const __half* __restrict__ Vh = g_vth + (size_t)bh * Dd * Nn;

    auto issueK = [&](int kt) {
        const int nn = kt * KROWS;
#pragma unroll
        for (int c = 0; c < 3; ++c) {
            const int chunk = tid + c * 256;       // KROWS*10 = 640
            if (chunk < KROWS * 10) {
                const int row = chunk / 10;
                const int kc  = chunk - row * 10;
                cp16(smem_u32(sKh + row * LDSK + kc * 8),
                     Kh + (size_t)(nn + row) * DP + kc * 8);
            }
        }
        CP_COMMIT();
    };
    auto issueV = [&](int kt) {
        const int nn = kt * KROWS;
#pragma unroll
        for (int c = 0; c < 3; ++c) {
            const int chunk = tid + c * 256;       // Dd*8 = 576
            if (chunk < Dd * 8) {
                const int row = chunk >> 3;
                const int kc  = chunk & 7;
                cp16(smem_u32(sVh + row * LDSV + kc * 8),
                     Vh + (size_t)row * Nn + nn + kc * 8);
            }
        }
        CP_COMMIT();
    };

    issueK(0);
#pragma unroll
    for (int c = 0; c < 5; ++c) {
        const int chunk = tid + c * 256;
        const int row = chunk / 10;
        const int kc  = chunk - row * 10;
        const int soff = row * LDSK + kc * 8;
        const size_t gq = (size_t)(m0 + row) * DP + kc * 8;
        *reinterpret_cast<uint4*>(&sQh[soff]) = *reinterpret_cast<const uint4*>(&Qh[gq]);
        *reinterpret_cast<uint4*>(&sQl[soff]) = *reinterpret_cast<const uint4*>(&Ql[gq]);
    }

    float m_run0 = -3.4e38f, m_run1 = -3.4e38f;
    float l_run0 = 0.f, l_run1 = 0.f;
    float o[9][4] = {};

    for (int kt = 0; kt < Nn / KROWS; ++kt) {
        CP_WAIT(0);
        __syncthreads();

        issueV(kt);

        // S = Q K^T, 2-pass fp16
        float s[8][4];
#pragma unroll
        for (int nf = 0; nf < 8; ++nf)
            s[nf][0] = s[nf][1] = s[nf][2] = s[nf][3] = 0.f;
#pragma unroll
        for (int ks = 0; ks < DP; ks += 16) {
            uint32_t aH[4], aL[4], b[2][2];
            const uint32_t aoff = ((wm + aRow) * LDSK + ks + aK) * 2;
            ldsm4(aH[0], aH[1], aH[2], aH[3], uQh + aoff);
            ldsm4(aL[0], aL[1], aL[2], aL[3], uQl + aoff);
#pragma unroll
            for (int np = 0; np < 4; ++np) {
                const uint32_t boff = ((np * 16 + bRow) * LDSK + ks + bK) * 2;
                ldsm4(b[0][0], b[0][1], b[1][0], b[1][1], uKh + boff);
                mma16816(s[2 * np],     aH, b[0]);
                mma16816(s[2 * np],     aL, b[0]);
                mma16816(s[2 * np + 1], aH, b[1]);
                mma16816(s[2 * np + 1], aL, b[1]);
            }
        }

        float mt0 = -3.4e38f, mt1 = -3.4e38f;
#pragma unroll
        for (int nf = 0; nf < 8; ++nf) {
            mt0 = fmaxf(mt0, fmaxf(s[nf][0], s[nf][1]));
            mt1 = fmaxf(mt1, fmaxf(s[nf][2], s[nf][3]));
        }
        mt0 = fmaxf(mt0, __shfl_xor_sync(0xffffffffu, mt0, 1));
        mt0 = fmaxf(mt0, __shfl_xor_sync(0xffffffffu, mt0, 2));
        mt1 = fmaxf(mt1, __shfl_xor_sync(0xffffffffu, mt1, 1));
        mt1 = fmaxf(mt1, __shfl_xor_sync(0xffffffffu, mt1, 2));
        const float mn0 = fmaxf(m_run0, mt0);
        const float mn1 = fmaxf(m_run1, mt1);
        const float sc0 = __expf(m_run0 - mn0);
        const float sc1 = __expf(m_run1 - mn1);
        m_run0 = mn0;
        m_run1 = mn1;
#pragma unroll
        for (int nf = 0; nf < 9; ++nf) {
            o[nf][0] *= sc0; o[nf][1] *= sc0;
            o[nf][2] *= sc1; o[nf][3] *= sc1;
        }

        CP_WAIT(0);
        __syncthreads();

        if (kt + 1 < Nn / KROWS) issueK(kt + 1);

        float ps0 = 0.f, ps1 = 0.f;
        // per k16-chunk: exp + exact P split (hi/lo) + 2-pass PV with Vh
#pragma unroll
        for (int kc = 0; kc < 4; ++kc) {
            const int nf0 = 2 * kc, nf1 = 2 * kc + 1;
            const float p00 = __expf(s[nf0][0] - mn0), p01 = __expf(s[nf0][1] - mn0);
            const float p02 = __expf(s[nf0][2] - mn1), p03 = __expf(s[nf0][3] - mn1);
            const float p10 = __expf(s[nf1][0] - mn0), p11 = __expf(s[nf1][1] - mn0);
            const float p12 = __expf(s[nf1][2] - mn1), p13 = __expf(s[nf1][3] - mn1);
            ps0 += p00 + p01 + p10 + p11;
            ps1 += p02 + p03 + p12 + p13;
            uint32_t pH[4], pL[4];
            pack_hilo(p00, p01, pH[0], pL[0]);
            pack_hilo(p02, p03, pH[1], pL[1]);
            pack_hilo(p10, p11, pH[2], pL[2]);
            pack_hilo(p12, p13, pH[3], pL[3]);

            uint32_t b[9][2];
#pragma unroll
            for (int np = 0; np < 4; ++np) {
                const uint32_t off = ((np * 16 + bRow) * LDSV + kc * 16 + bK) * 2;
                ldsm4(b[2 * np][0], b[2 * np][1], b[2 * np + 1][0], b[2 * np + 1][1], uVh + off);
            }
            {
                const uint32_t off = ((64 + lane7) * LDSV + kc * 16 + bK) * 2;
                ldsm2(b[8][0], b[8][1], uVh + off);
            }
#pragma unroll
            for (int nf = 0; nf < 9; ++nf) {
                mma16816(o[nf], pH, b[nf]);
                mma16816(o[nf], pL, b[nf]);
            }
        }
        ps0 += __shfl_xor_sync(0xffffffffu, ps0, 1);
        ps0 += __shfl_xor_sync(0xffffffffu, ps0, 2);
        ps1 += __shfl_xor_sync(0xffffffffu, ps1, 1);
        ps1 += __shfl_xor_sync(0xffffffffu, ps1, 2);
        l_run0 = l_run0 * sc0 + ps0;
        l_run1 = l_run1 * sc1 + ps1;
    }

    const float inv0 = 1.0f / l_run0;
    const float inv1 = 1.0f / l_run1;
    const int b = bh >> 4;
    const int h = bh & 15;
    const int tok0 = m0 + wm + gi;
#pragma unroll
    for (int nf = 0; nf < 9; ++nf) {
        const int col = nf * 8 + tig * 2;
        const size_t o0 = ((size_t)(b * Nn + tok0)) * HID + h * Dd + col;
        const size_t o1 = ((size_t)(b * Nn + tok0 + 8)) * HID + h * Dd + col;
        const float x0 = o[nf][0] * inv0, y0 = o[nf][1] * inv0;
        const float x1 = o[nf][2] * inv1, y1 = o[nf][3] * inv1;
        *reinterpret_cast<__half2*>(&g_oa_hi[o0]) = hilo2(x0, y0, false);
        *reinterpret_cast<__half2*>(&g_oa_lo[o0]) = hilo2(x0, y0, true);
        *reinterpret_cast<__half2*>(&g_oa_hi[o1]) = hilo2(x1, y1, false);
        *reinterpret_cast<__half2*>(&g_oa_lo[o1]) = hilo2(x1, y1, true);
    }
}

// ---------------------------------------------------------------------------
extern "C" void kernel_launch(void* const* d_in, const int* in_sizes, int n_in,
                              void* d_out, int out_size) {
    const float* x     = (const float*)d_in[0];
    const float* w_qkv = (const float*)d_in[1];
    const float* b_qkv = (const float*)d_in[2];
    const float* w_out = (const float*)d_in[3];
    const float* b_out = (const float*)d_in[4];
    float* out = (float*)d_out;

    cudaFuncSetAttribute(k_flash, cudaFuncAttributeMaxDynamicSharedMemorySize, FLASH_SMEM);
    cudaFuncSetAttribute(k_gemm<0>, cudaFuncAttributeMaxDynamicSharedMemorySize, GEMM_SMEM);
    cudaFuncSetAttribute(k_gemm<1>, cudaFuncAttributeMaxDynamicSharedMemorySize, GEMM_SMEM);

    const int n4 = MTOK * HID / 4;

    // prep
    k_zpad<<<(BHEAD * Nn + 255) / 256, 256>>>();
    k_split<<<(n4 + 255) / 256, 256>>>(x);
    k_tsplit<QKVN, 0><<<dim3(QKVN / 32, HID / 32), dim3(32, 8)>>>(w_qkv);
    k_tsplit<HID, 1><<<dim3(HID / 32, HID / 32), dim3(32, 8)>>>(w_out);

    // 1. QKV projection -> Q(scaled) hi/lo (padded), K fp16, V^T fp16
    k_gemm<0><<<dim3(QKVN / 128, MTOK / 128), 256, GEMM_SMEM>>>(b_qkv, nullptr);

    // 2. fused flash attention -> g_oa hi/lo
    k_flash<<<dim3(Nn / 128, BHEAD), 256, FLASH_SMEM>>>();

    // 3. output projection
    k_gemm<1><<<dim3(HID / 128, MTOK / 128), 256, GEMM_SMEM>>>(b_out, out);
}

// round 13
// speedup vs baseline: 1.9386x; 1.3856x over previous
#include <cuda_runtime.h>
#include <cuda_fp16.h>
#include <cstdint>

// ---------------------------------------------------------------------------
// Attention_21474836480706: B=4, N=1024, H=16, D=72, HID=1152 (fp32)
// R13: projections single-pass fp16 A (x, attn-out stored as plain fp16);
// flash keeps Q/P hi/lo. Calibrated error budget ~5.5-6.5e-4 < 1e-3.
// ---------------------------------------------------------------------------

namespace {
constexpr int Bb    = 4;
constexpr int Nn    = 1024;
constexpr int Hh    = 16;
constexpr int Dd    = 72;
constexpr int DP    = 80;
constexpr int HID   = 1152;
constexpr int ATT   = Hh * Dd;        // 1152
constexpr int MTOK  = Bb * Nn;        // 4096
constexpr int QKVN  = 3 * ATT;        // 3456
constexpr int BHEAD = Bb * Hh;        // 64
}

// ------------------------------ scratch ------------------------------------
__device__ __align__(16) __half g_qh[(size_t)BHEAD * Nn * DP];   // Q hi (pre-scaled)
__device__ __align__(16) __half g_ql[(size_t)BHEAD * Nn * DP];   // Q lo
__device__ __align__(16) __half g_kh[(size_t)BHEAD * Nn * DP];   // K (single fp16)
__device__ __align__(16) __half g_vth[(size_t)BHEAD * Dd * Nn];  // V^T (single fp16)

__device__ __align__(16) __half g_xa[(size_t)MTOK * HID];        // x (single fp16)
__device__ __align__(16) __half g_oa[(size_t)MTOK * HID];        // attn out (single fp16)
__device__ __align__(16) __half g_wqkvt[(size_t)QKVN * HID];     // W_qkv^T fp16
__device__ __align__(16) __half g_wot[(size_t)HID * HID];        // W_out^T fp16

// --------------------------- helpers ---------------------------------------
__device__ __forceinline__ uint32_t smem_u32(const void* p) {
    uint32_t a;
    asm("{ .reg .u64 t; cvta.to.shared.u64 t, %1; cvt.u32.u64 %0, t; }" : "=r"(a) : "l"(p));
    return a;
}
__device__ __forceinline__ void cp16(uint32_t s, const void* g) {
    asm volatile("cp.async.cg.shared.global [%0], [%1], 16;" :: "r"(s), "l"(g));
}
#define CP_COMMIT() asm volatile("cp.async.commit_group;" ::: "memory")
#define CP_WAIT(n)  asm volatile("cp.async.wait_group %0;" :: "n"(n) : "memory")

__device__ __forceinline__ void ldsm4(uint32_t& r0, uint32_t& r1, uint32_t& r2, uint32_t& r3,
                                      uint32_t a) {
    asm volatile("ldmatrix.sync.aligned.m8n8.x4.shared.b16 {%0,%1,%2,%3}, [%4];"
                 : "=r"(r0), "=r"(r1), "=r"(r2), "=r"(r3) : "r"(a));
}
__device__ __forceinline__ void ldsm2(uint32_t& r0, uint32_t& r1, uint32_t a) {
    asm volatile("ldmatrix.sync.aligned.m8n8.x2.shared.b16 {%0,%1}, [%2];"
                 : "=r"(r0), "=r"(r1) : "r"(a));
}
__device__ __forceinline__ void mma16816(float* d, const uint32_t* a, const uint32_t* b) {
    asm volatile(
        "mma.sync.aligned.m16n8k16.row.col.f32.f16.f16.f32 "
        "{%0,%1,%2,%3}, {%4,%5,%6,%7}, {%8,%9}, {%0,%1,%2,%3};"
        : "+f"(d[0]), "+f"(d[1]), "+f"(d[2]), "+f"(d[3])
        : "r"(a[0]), "r"(a[1]), "r"(a[2]), "r"(a[3]), "r"(b[0]), "r"(b[1]));
}
__device__ __forceinline__ __half2 hilo2(float a, float b, bool lo) {
    __half ha = __float2half(a), hb = __float2half(b);
    if (!lo) return __halves2half2(ha, hb);
    return __halves2half2(__float2half(a - __half2float(ha)),
                          __float2half(b - __half2float(hb)));
}
__device__ __forceinline__ void pack_hilo(float a, float b, uint32_t& hi, uint32_t& lo) {
    __half ha = __float2half(a), hb = __float2half(b);
    __half2 h2 = __halves2half2(ha, hb);
    __half2 l2 = __halves2half2(__float2half(a - __half2float(ha)),
                                __float2half(b - __half2float(hb)));
    hi = *reinterpret_cast<uint32_t*>(&h2);
    lo = *reinterpret_cast<uint32_t*>(&l2);
}

// ---------------------------------------------------------------------------
// split/convert x + zero D-padding (fused; pad blocks are the first 256)
// ---------------------------------------------------------------------------
__global__ __launch_bounds__(256) void k_split(const float* __restrict__ in) {
    const int n4 = MTOK * HID / 4;
    const int i = blockIdx.x * 256 + threadIdx.x;
    if (i < n4) {
        float4 v = reinterpret_cast<const float4*>(in)[i];
        __half2 a = __halves2half2(__float2half(v.x), __float2half(v.y));
        __half2 b = __halves2half2(__float2half(v.z), __float2half(v.w));
        reinterpret_cast<__half2*>(g_xa)[2 * i]     = a;
        reinterpret_cast<__half2*>(g_xa)[2 * i + 1] = b;
    }
    if (i < BHEAD * Nn) {   // zero D-pad of Q hi/lo + K
        const size_t o = (size_t)i * DP + Dd;
        const uint4 z = make_uint4(0, 0, 0, 0);
        *reinterpret_cast<uint4*>(&g_qh[o]) = z;
        *reinterpret_cast<uint4*>(&g_ql[o]) = z;
        *reinterpret_cast<uint4*>(&g_kh[o]) = z;
    }
}

// transpose: W[K][NCOLS] fp32 -> Wt [NCOLS][K=1152] fp16
template <int NCOLS, int WHICH>
__global__ void k_tsplit(const float* __restrict__ W) {
    __shared__ float t[32][33];
    const int n0 = blockIdx.x * 32, k0 = blockIdx.y * 32;
    const int tx = threadIdx.x, ty = threadIdx.y;   // (32, 8)
#pragma unroll
    for (int i = 0; i < 4; ++i)
        t[ty * 4 + i][tx] = W[(size_t)(k0 + ty * 4 + i) * NCOLS + n0 + tx];
    __syncthreads();
    __half* Hi = WHICH ? g_wot : g_wqkvt;
#pragma unroll
    for (int i = 0; i < 4; ++i)
        Hi[(size_t)(n0 + ty * 4 + i) * HID + k0 + tx] = __float2half(t[tx][ty * 4 + i]);
}

// ---------------------------------------------------------------------------
// HMMA GEMM (projections): single-pass fp16. smem per stage: A, B (2 tiles).
// ---------------------------------------------------------------------------
namespace {
constexpr int GBM = 128, GBK = 32, GLDS = 40;
constexpr int GTILE = GBM * GLDS;
constexpr int GSTAGE = 2 * GTILE;
constexpr int GEMM_SMEM = 2 * GSTAGE * 2;         // 40960 B
}

template <int MODE>
__global__ __launch_bounds__(256, 2) void k_gemm(const float* __restrict__ bias,
                                                 float* __restrict__ Cout) {
    extern __shared__ __half gsm[];

    const int tid  = threadIdx.x;
    const int warp = tid >> 5, lane = tid & 31;
    const int wm = (warp >> 2) * 64;
    const int wn = (warp & 3) * 32;
    const int gi  = lane >> 2;
    const int tig = lane & 3;
    const int m0 = blockIdx.y * GBM;
    const int n0 = blockIdx.x * GBM;

    const int lane7 = lane & 7;
    const int aRow = lane7 + ((lane & 8) ? 8 : 0);
    const int aK   = (lane & 16) ? 8 : 0;
    const int bRow = lane7 + ((lane & 16) ? 8 : 0);
    const int bK   = (lane & 8) ? 8 : 0;

    const __half* __restrict__ Ah = MODE ? g_oa : g_xa;
    const __half* __restrict__ Bh = MODE ? g_wot : g_wqkvt;

    const int r0c = tid >> 2, k0c = (tid & 3);
    const int r1c = (tid + 256) >> 2, k1c = (tid & 3);

    auto issue_tile = [&](int kt, int stage) {
        __half* base = gsm + stage * GSTAGE;
        const int kk = kt * GBK;
#pragma unroll
        for (int c = 0; c < 2; ++c) {
            const int row = c ? r1c : r0c;
            const int kc  = c ? k1c : k0c;
            const uint32_t soff = smem_u32(base + row * GLDS + kc * 8);
            cp16(soff,             Ah + (size_t)(m0 + row) * HID + kk + kc * 8);
            cp16(soff + GTILE * 2, Bh + (size_t)(n0 + row) * HID + kk + kc * 8);
        }
        CP_COMMIT();
    };

    float acc[4][4][4] = {};
    constexpr int NT = HID / GBK;   // 36

    issue_tile(0, 0);

    for (int t = 0; t < NT; ++t) {
        if (t + 1 < NT) {
            issue_tile(t + 1, (t + 1) & 1);
            CP_WAIT(1);
        } else {
            CP_WAIT(0);
        }
        __syncthreads();

        const uint32_t uAh = smem_u32(gsm + (t & 1) * GSTAGE);
        const uint32_t uBh = uAh + GTILE * 2;

#pragma unroll
        for (int ks = 0; ks < GBK; ks += 16) {
            uint32_t b[4][2];
#pragma unroll
            for (int np = 0; np < 2; ++np) {
                const uint32_t off = ((wn + np * 16 + bRow) * GLDS + ks + bK) * 2;
                ldsm4(b[2 * np][0], b[2 * np][1], b[2 * np + 1][0], b[2 * np + 1][1],
                      uBh + off);
            }
#pragma unroll
            for (int mf = 0; mf < 4; ++mf) {
                uint32_t ah[4];
                const uint32_t off = ((wm + mf * 16 + aRow) * GLDS + ks + aK) * 2;
                ldsm4(ah[0], ah[1], ah[2], ah[3], uAh + off);
#pragma unroll
                for (int nf = 0; nf < 4; ++nf)
                    mma16816(acc[mf][nf], ah, b[nf]);
            }
        }
        __syncthreads();
    }

    const float qscale = 0.11785113019775793f;  // 1/sqrt(72)
#pragma unroll
    for (int mf = 0; mf < 4; ++mf) {
#pragma unroll
        for (int nf = 0; nf < 4; ++nf) {
            const int row = m0 + wm + mf * 16 + gi;
            const int col = n0 + wn + nf * 8 + tig * 2;
            const float b0 = bias[col], b1 = bias[col + 1];
            float x0 = acc[mf][nf][0] + b0, y0 = acc[mf][nf][1] + b1;
            float x1 = acc[mf][nf][2] + b0, y1 = acc[mf][nf][3] + b1;
            if (MODE == 0) {
                const int which = n0 / ATT;
                const int rem = col - which * ATT;
                const int h = rem / Dd, d = rem - h * Dd;
                const int bb = row >> 10, tok = row & 1023;
                const int bh = bb * Hh + h;
                if (which == 0) {
                    x0 *= qscale; y0 *= qscale; x1 *= qscale; y1 *= qscale;
                    const size_t o0 = ((size_t)bh * Nn + tok) * DP + d;
                    const size_t o1 = o0 + 8 * DP;
                    *reinterpret_cast<__half2*>(&g_qh[o0]) = hilo2(x0, y0, false);
                    *reinterpret_cast<__half2*>(&g_ql[o0]) = hilo2(x0, y0, true);
                    *reinterpret_cast<__half2*>(&g_qh[o1]) = hilo2(x1, y1, false);
                    *reinterpret_cast<__half2*>(&g_ql[o1]) = hilo2(x1, y1, true);
                } else if (which == 1) {
                    const size_t o0 = ((size_t)bh * Nn + tok) * DP + d;
                    const size_t o1 = o0 + 8 * DP;
                    *reinterpret_cast<__half2*>(&g_kh[o0]) = hilo2(x0, y0, false);
                    *reinterpret_cast<__half2*>(&g_kh[o1]) = hilo2(x1, y1, false);
                } else {
                    const size_t b0o = ((size_t)bh * Dd + d) * Nn + tok;
                    const size_t b1o = b0o + Nn;
                    g_vth[b0o]     = __float2half(x0);
                    g_vth[b1o]     = __float2half(y0);
                    g_vth[b0o + 8] = __float2half(x1);
                    g_vth[b1o + 8] = __float2half(y1);
                }
            } else {
                *reinterpret_cast<float2*>(&Cout[(size_t)row * HID + col]) = make_float2(x0, y0);
                *reinterpret_cast<float2*>(&Cout[(size_t)(row + 8) * HID + col]) = make_float2(x1, y1);
            }
        }
    }
}

// ---------------------------------------------------------------------------
// Flash attention (as R12): fp16 2-pass (Q hi/lo, P hi/lo), K/V single fp16.
// Output now single fp16 (g_oa).
// ---------------------------------------------------------------------------
namespace {
constexpr int LDSK  = 88;
constexpr int LDSV  = 72;
constexpr int KROWS = 64;
constexpr int QELE  = 128 * LDSK;
constexpr int KELE  = KROWS * LDSK;
constexpr int VELE  = Dd * LDSV;
constexpr int FLASH_SMEM = (2 * QELE + KELE + VELE) * 2;   // 66688 B
}

__global__ __launch_bounds__(256, 2) void k_flash() {
    extern __shared__ __half sm[];
    __half* sQh = sm;
    __half* sQl = sm + QELE;
    __half* sKh = sm + 2 * QELE;
    __half* sVh = sm + 2 * QELE + KELE;

    const int tid  = threadIdx.x;
    const int warp = tid >> 5, lane = tid & 31;
    const int wm  = warp * 16;
    const int gi  = lane >> 2;
    const int tig = lane & 3;
    const int bh = blockIdx.y;
    const int m0 = blockIdx.x * 128;

    const int lane7 = lane & 7;
    const int aRow = lane7 + ((lane & 8) ? 8 : 0);
    const int aK   = (lane & 16) ? 8 : 0;
    const int bRow = lane7 + ((lane & 16) ? 8 : 0);
    const int bK   = (lane & 8) ? 8 : 0;

    const uint32_t uQh = smem_u32(sQh), uQl = smem_u32(sQl);
    const uint32_t uKh = smem_u32(sKh);
    const uint32_t uVh = smem_u32(sVh);

    const __half* __restrict__ Qh = g_qh + (size_t)bh * Nn * DP;
    const __half* __restrict__ Ql = g_ql + (size_t)bh * Nn * DP;
    const __half* __restrict__ Kh = g_kh + (size_t)bh * Nn * DP;
    const __half* __restrict__ Vh = g_vth + (size_t)bh * Dd * Nn;

    auto issueK = [&](int kt) {
        const int nn = kt * KROWS;
#pragma unroll
        for (int c = 0; c < 3; ++c) {
            const int chunk = tid + c * 256;       // KROWS*10 = 640
            if (chunk < KROWS * 10) {
                const int row = chunk / 10;
                const int kc  = chunk - row * 10;
                cp16(smem_u32(sKh + row * LDSK + kc * 8),
                     Kh + (size_t)(nn + row) * DP + kc * 8);
            }
        }
        CP_COMMIT();
    };
    auto issueV = [&](int kt) {
        const int nn = kt * KROWS;
#pragma unroll
        for (int c = 0; c < 3; ++c) {
            const int chunk = tid + c * 256;       // Dd*8 = 576
            if (chunk < Dd * 8) {
                const int row = chunk >> 3;
                const int kc  = chunk & 7;
                cp16(smem_u32(sVh + row * LDSV + kc * 8),
                     Vh + (size_t)row * Nn + nn + kc * 8);
            }
        }
        CP_COMMIT();
    };

    issueK(0);
#pragma unroll
    for (int c = 0; c < 5; ++c) {
        const int chunk = tid + c * 256;
        const int row = chunk / 10;
        const int kc  = chunk - row * 10;
        const int soff = row * LDSK + kc * 8;
        const size_t gq = (size_t)(m0 + row) * DP + kc * 8;
        *reinterpret_cast<uint4*>(&sQh[soff]) = *reinterpret_cast<const uint4*>(&Qh[gq]);
        *reinterpret_cast<uint4*>(&sQl[soff]) = *reinterpret_cast<const uint4*>(&Ql[gq]);
    }

    float m_run0 = -3.4e38f, m_run1 = -3.4e38f;
    float l_run0 = 0.f, l_run1 = 0.f;
    float o[9][4] = {};

    for (int kt = 0; kt < Nn / KROWS; ++kt) {
        CP_WAIT(0);
        __syncthreads();

        issueV(kt);

        // S = Q K^T, 2-pass fp16
        float s[8][4];
#pragma unroll
        for (int nf = 0; nf < 8; ++nf)
            s[nf][0] = s[nf][1] = s[nf][2] = s[nf][3] = 0.f;
#pragma unroll
        for (int ks = 0; ks < DP; ks += 16) {
            uint32_t aH[4], aL[4], b[2][2];
            const uint32_t aoff = ((wm + aRow) * LDSK + ks + aK) * 2;
            ldsm4(aH[0], aH[1], aH[2], aH[3], uQh + aoff);
            ldsm4(aL[0], aL[1], aL[2], aL[3], uQl + aoff);
#pragma unroll
            for (int np = 0; np < 4; ++np) {
                const uint32_t boff = ((np * 16 + bRow) * LDSK + ks + bK) * 2;
                ldsm4(b[0][0], b[0][1], b[1][0], b[1][1], uKh + boff);
                mma16816(s[2 * np],     aH, b[0]);
                mma16816(s[2 * np],     aL, b[0]);
                mma16816(s[2 * np + 1], aH, b[1]);
                mma16816(s[2 * np + 1], aL, b[1]);
            }
        }

        float mt0 = -3.4e38f, mt1 = -3.4e38f;
#pragma unroll
        for (int nf = 0; nf < 8; ++nf) {
            mt0 = fmaxf(mt0, fmaxf(s[nf][0], s[nf][1]));
            mt1 = fmaxf(mt1, fmaxf(s[nf][2], s[nf][3]));
        }
        mt0 = fmaxf(mt0, __shfl_xor_sync(0xffffffffu, mt0, 1));
        mt0 = fmaxf(mt0, __shfl_xor_sync(0xffffffffu, mt0, 2));
        mt1 = fmaxf(mt1, __shfl_xor_sync(0xffffffffu, mt1, 1));
        mt1 = fmaxf(mt1, __shfl_xor_sync(0xffffffffu, mt1, 2));
        const float mn0 = fmaxf(m_run0, mt0);
        const float mn1 = fmaxf(m_run1, mt1);
        const float sc0 = __expf(m_run0 - mn0);
        const float sc1 = __expf(m_run1 - mn1);
        m_run0 = mn0;
        m_run1 = mn1;
#pragma unroll
        for (int nf = 0; nf < 9; ++nf) {
            o[nf][0] *= sc0; o[nf][1] *= sc0;
            o[nf][2] *= sc1; o[nf][3] *= sc1;
        }

        CP_WAIT(0);
        __syncthreads();

        if (kt + 1 < Nn / KROWS) issueK(kt + 1);

        float ps0 = 0.f, ps1 = 0.f;
#pragma unroll
        for (int kc = 0; kc < 4; ++kc) {
            const int nf0 = 2 * kc, nf1 = 2 * kc + 1;
            const float p00 = __expf(s[nf0][0] - mn0), p01 = __expf(s[nf0][1] - mn0);
            const float p02 = __expf(s[nf0][2] - mn1), p03 = __expf(s[nf0][3] - mn1);
            const float p10 = __expf(s[nf1][0] - mn0), p11 = __expf(s[nf1][1] - mn0);
            const float p12 = __expf(s[nf1][2] - mn1), p13 = __expf(s[nf1][3] - mn1);
            ps0 += p00 + p01 + p10 + p11;
            ps1 += p02 + p03 + p12 + p13;
            uint32_t pH[4], pL[4];
            pack_hilo(p00, p01, pH[0], pL[0]);
            pack_hilo(p02, p03, pH[1], pL[1]);
            pack_hilo(p10, p11, pH[2], pL[2]);
            pack_hilo(p12, p13, pH[3], pL[3]);

            uint32_t b[9][2];
#pragma unroll
            for (int np = 0; np < 4; ++np) {
                const uint32_t off = ((np * 16 + bRow) * LDSV + kc * 16 + bK) * 2;
                ldsm4(b[2 * np][0], b[2 * np][1], b[2 * np + 1][0], b[2 * np + 1][1], uVh + off);
            }
            {
                const uint32_t off = ((64 + lane7) * LDSV + kc * 16 + bK) * 2;
                ldsm2(b[8][0], b[8][1], uVh + off);
            }
#pragma unroll
            for (int nf = 0; nf < 9; ++nf) {
                mma16816(o[nf], pH, b[nf]);
                mma16816(o[nf], pL, b[nf]);
            }
        }
        ps0 += __shfl_xor_sync(0xffffffffu, ps0, 1);
        ps0 += __shfl_xor_sync(0xffffffffu, ps0, 2);
        ps1 += __shfl_xor_sync(0xffffffffu, ps1, 1);
        ps1 += __shfl_xor_sync(0xffffffffu, ps1, 2);
        l_run0 = l_run0 * sc0 + ps0;
        l_run1 = l_run1 * sc1 + ps1;
    }

    const float inv0 = 1.0f / l_run0;
    const float inv1 = 1.0f / l_run1;
    const int b = bh >> 4;
    const int h = bh & 15;
    const int tok0 = m0 + wm + gi;
#pragma unroll
    for (int nf = 0; nf < 9; ++nf) {
        const int col = nf * 8 + tig * 2;
        const size_t o0 = ((size_t)(b * Nn + tok0)) * HID + h * Dd + col;
        const size_t o1 = ((size_t)(b * Nn + tok0 + 8)) * HID + h * Dd + col;
        *reinterpret_cast<__half2*>(&g_oa[o0]) =
            __halves2half2(__float2half(o[nf][0] * inv0), __float2half(o[nf][1] * inv0));
        *reinterpret_cast<__half2*>(&g_oa[o1]) =
            __halves2half2(__float2half(o[nf][2] * inv1), __float2half(o[nf][3] * inv1));
    }
}

// ---------------------------------------------------------------------------
extern "C" void kernel_launch(void* const* d_in, const int* in_sizes, int n_in,
                              void* d_out, int out_size) {
    const float* x     = (const float*)d_in[0];
    const float* w_qkv = (const float*)d_in[1];
    const float* b_qkv = (const float*)d_in[2];
    const float* w_out = (const float*)d_in[3];
    const float* b_out = (const float*)d_in[4];
    float* out = (float*)d_out;

    cudaFuncSetAttribute(k_flash, cudaFuncAttributeMaxDynamicSharedMemorySize, FLASH_SMEM);
    cudaFuncSetAttribute(k_gemm<0>, cudaFuncAttributeMaxDynamicSharedMemorySize, GEMM_SMEM);
    cudaFuncSetAttribute(k_gemm<1>, cudaFuncAttributeMaxDynamicSharedMemorySize, GEMM_SMEM);

    const int n4 = MTOK * HID / 4;

    // prep (split+zpad fused; weight transposes)
    k_split<<<(n4 + 255) / 256, 256>>>(x);
    k_tsplit<QKVN, 0><<<dim3(QKVN / 32, HID / 32), dim3(32, 8)>>>(w_qkv);
    k_tsplit<HID, 1><<<dim3(HID / 32, HID / 32), dim3(32, 8)>>>(w_out);

    // 1. QKV projection -> Q(scaled) hi/lo (padded), K fp16, V^T fp16
    k_gemm<0><<<dim3(QKVN / 128, MTOK / 128), 256, GEMM_SMEM>>>(b_qkv, nullptr);

    // 2. fused flash attention -> g_oa fp16
    k_flash<<<dim3(Nn / 128, BHEAD), 256, FLASH_SMEM>>>();

    // 3. output projection
    k_gemm<1><<<dim3(HID / 128, MTOK / 128), 256, GEMM_SMEM>>>(b_out, out);
}

// round 14
// speedup vs baseline: 2.2428x; 1.1570x over previous
#include <cuda_runtime.h>
#include <cuda_fp16.h>
#include <cstdint>

// ---------------------------------------------------------------------------
// Attention_21474836480706: B=4, N=1024, H=16, D=72, HID=1152 (fp32)
// R14: flash PV single-pass (P plain fp16); gemm GBK=64 (half the syncs).
// Error budget (calibrated): ~6.0e-4 < 1e-3.
// ---------------------------------------------------------------------------

namespace {
constexpr int Bb    = 4;
constexpr int Nn    = 1024;
constexpr int Hh    = 16;
constexpr int Dd    = 72;
constexpr int DP    = 80;
constexpr int HID   = 1152;
constexpr int ATT   = Hh * Dd;        // 1152
constexpr int MTOK  = Bb * Nn;        // 4096
constexpr int QKVN  = 3 * ATT;        // 3456
constexpr int BHEAD = Bb * Hh;        // 64
}

// ------------------------------ scratch ------------------------------------
__device__ __align__(16) __half g_qh[(size_t)BHEAD * Nn * DP];   // Q hi (pre-scaled)
__device__ __align__(16) __half g_ql[(size_t)BHEAD * Nn * DP];   // Q lo
__device__ __align__(16) __half g_kh[(size_t)BHEAD * Nn * DP];   // K fp16
__device__ __align__(16) __half g_vth[(size_t)BHEAD * Dd * Nn];  // V^T fp16

__device__ __align__(16) __half g_xa[(size_t)MTOK * HID];        // x fp16
__device__ __align__(16) __half g_oa[(size_t)MTOK * HID];        // attn out fp16
__device__ __align__(16) __half g_wqkvt[(size_t)QKVN * HID];     // W_qkv^T fp16
__device__ __align__(16) __half g_wot[(size_t)HID * HID];        // W_out^T fp16

// --------------------------- helpers ---------------------------------------
__device__ __forceinline__ uint32_t smem_u32(const void* p) {
    uint32_t a;
    asm("{ .reg .u64 t; cvta.to.shared.u64 t, %1; cvt.u32.u64 %0, t; }" : "=r"(a) : "l"(p));
    return a;
}
__device__ __forceinline__ void cp16(uint32_t s, const void* g) {
    asm volatile("cp.async.cg.shared.global [%0], [%1], 16;" :: "r"(s), "l"(g));
}
#define CP_COMMIT() asm volatile("cp.async.commit_group;" ::: "memory")
#define CP_WAIT(n)  asm volatile("cp.async.wait_group %0;" :: "n"(n) : "memory")

__device__ __forceinline__ void ldsm4(uint32_t& r0, uint32_t& r1, uint32_t& r2, uint32_t& r3,
                                      uint32_t a) {
    asm volatile("ldmatrix.sync.aligned.m8n8.x4.shared.b16 {%0,%1,%2,%3}, [%4];"
                 : "=r"(r0), "=r"(r1), "=r"(r2), "=r"(r3) : "r"(a));
}
__device__ __forceinline__ void ldsm2(uint32_t& r0, uint32_t& r1, uint32_t a) {
    asm volatile("ldmatrix.sync.aligned.m8n8.x2.shared.b16 {%0,%1}, [%2];"
                 : "=r"(r0), "=r"(r1) : "r"(a));
}
__device__ __forceinline__ void mma16816(float* d, const uint32_t* a, const uint32_t* b) {
    asm volatile(
        "mma.sync.aligned.m16n8k16.row.col.f32.f16.f16.f32 "
        "{%0,%1,%2,%3}, {%4,%5,%6,%7}, {%8,%9}, {%0,%1,%2,%3};"
        : "+f"(d[0]), "+f"(d[1]), "+f"(d[2]), "+f"(d[3])
        : "r"(a[0]), "r"(a[1]), "r"(a[2]), "r"(a[3]), "r"(b[0]), "r"(b[1]));
}
__device__ __forceinline__ __half2 hilo2(float a, float b, bool lo) {
    __half ha = __float2half(a), hb = __float2half(b);
    if (!lo) return __halves2half2(ha, hb);
    return __halves2half2(__float2half(a - __half2float(ha)),
                          __float2half(b - __half2float(hb)));
}
__device__ __forceinline__ uint32_t pack2(float a, float b) {
    __half2 h2 = __halves2half2(__float2half(a), __float2half(b));
    return *reinterpret_cast<uint32_t*>(&h2);
}

// ---------------------------------------------------------------------------
// convert x fp32 -> fp16 + zero D-padding of Q/K (fused)
// ---------------------------------------------------------------------------
__global__ __launch_bounds__(256) void k_split(const float* __restrict__ in) {
    const int n4 = MTOK * HID / 4;
    const int i = blockIdx.x * 256 + threadIdx.x;
    if (i < n4) {
        float4 v = reinterpret_cast<const float4*>(in)[i];
        reinterpret_cast<__half2*>(g_xa)[2 * i] =
            __halves2half2(__float2half(v.x), __float2half(v.y));
        reinterpret_cast<__half2*>(g_xa)[2 * i + 1] =
            __halves2half2(__float2half(v.z), __float2half(v.w));
    }
    if (i < BHEAD * Nn) {
        const size_t o = (size_t)i * DP + Dd;
        const uint4 z = make_uint4(0, 0, 0, 0);
        *reinterpret_cast<uint4*>(&g_qh[o]) = z;
        *reinterpret_cast<uint4*>(&g_ql[o]) = z;
        *reinterpret_cast<uint4*>(&g_kh[o]) = z;
    }
}

// transpose: W[K][NCOLS] fp32 -> Wt [NCOLS][K=1152] fp16
template <int NCOLS, int WHICH>
__global__ void k_tsplit(const float* __restrict__ W) {
    __shared__ float t[32][33];
    const int n0 = blockIdx.x * 32, k0 = blockIdx.y * 32;
    const int tx = threadIdx.x, ty = threadIdx.y;   // (32, 8)
#pragma unroll
    for (int i = 0; i < 4; ++i)
        t[ty * 4 + i][tx] = W[(size_t)(k0 + ty * 4 + i) * NCOLS + n0 + tx];
    __syncthreads();
    __half* Hi = WHICH ? g_wot : g_wqkvt;
#pragma unroll
    for (int i = 0; i < 4; ++i)
        Hi[(size_t)(n0 + ty * 4 + i) * HID + k0 + tx] = __float2half(t[tx][ty * 4 + i]);
}

// ---------------------------------------------------------------------------
// HMMA GEMM (projections): single-pass fp16, GBK=64, 2-stage, 2 CTAs/SM.
// ---------------------------------------------------------------------------
namespace {
constexpr int GBM = 128, GBK = 64, GLDS = 72;     // 72*2=144B row stride: conflict-free ldsm
constexpr int GTILE = GBM * GLDS;                 // 9216 elems
constexpr int GSTAGE = 2 * GTILE;                 // A + B
constexpr int GEMM_SMEM = 2 * GSTAGE * 2;         // 73728 B
}

template <int MODE>
__global__ __launch_bounds__(256, 2) void k_gemm(const float* __restrict__ bias,
                                                 float* __restrict__ Cout) {
    extern __shared__ __half gsm[];

    const int tid  = threadIdx.x;
    const int warp = tid >> 5, lane = tid & 31;
    const int wm = (warp >> 2) * 64;
    const int wn = (warp & 3) * 32;
    const int gi  = lane >> 2;
    const int tig = lane & 3;
    const int m0 = blockIdx.y * GBM;
    const int n0 = blockIdx.x * GBM;

    const int lane7 = lane & 7;
    const int aRow = lane7 + ((lane & 8) ? 8 : 0);
    const int aK   = (lane & 16) ? 8 : 0;
    const int bRow = lane7 + ((lane & 16) ? 8 : 0);
    const int bK   = (lane & 8) ? 8 : 0;

    const __half* __restrict__ Ah = MODE ? g_oa : g_xa;
    const __half* __restrict__ Bh = MODE ? g_wot : g_wqkvt;

    auto issue_tile = [&](int kt, int stage) {
        __half* base = gsm + stage * GSTAGE;
        const int kk = kt * GBK;
#pragma unroll
        for (int c = 0; c < 4; ++c) {
            const int chunk = tid + c * 256;      // 0..1023
            const int row = chunk >> 3;           // 0..127
            const int kc  = chunk & 7;            // 0..7 (8-elem units)
            const uint32_t soff = smem_u32(base + row * GLDS + kc * 8);
            cp16(soff,             Ah + (size_t)(m0 + row) * HID + kk + kc * 8);
            cp16(soff + GTILE * 2, Bh + (size_t)(n0 + row) * HID + kk + kc * 8);
        }
        CP_COMMIT();
    };

    float acc[4][4][4] = {};
    constexpr int NT = HID / GBK;   // 18

    issue_tile(0, 0);

    for (int t = 0; t < NT; ++t) {
        if (t + 1 < NT) {
            issue_tile(t + 1, (t + 1) & 1);
            CP_WAIT(1);
        } else {
            CP_WAIT(0);
        }
        __syncthreads();

        const uint32_t uAh = smem_u32(gsm + (t & 1) * GSTAGE);
        const uint32_t uBh = uAh + GTILE * 2;

#pragma unroll
        for (int ks = 0; ks < GBK; ks += 16) {
            uint32_t b[4][2];
#pragma unroll
            for (int np = 0; np < 2; ++np) {
                const uint32_t off = ((wn + np * 16 + bRow) * GLDS + ks + bK) * 2;
                ldsm4(b[2 * np][0], b[2 * np][1], b[2 * np + 1][0], b[2 * np + 1][1],
                      uBh + off);
            }
#pragma unroll
            for (int mf = 0; mf < 4; ++mf) {
                uint32_t ah[4];
                const uint32_t off = ((wm + mf * 16 + aRow) * GLDS + ks + aK) * 2;
                ldsm4(ah[0], ah[1], ah[2], ah[3], uAh + off);
#pragma unroll
                for (int nf = 0; nf < 4; ++nf)
                    mma16816(acc[mf][nf], ah, b[nf]);
            }
        }
        __syncthreads();
    }

    const float qscale = 0.11785113019775793f;  // 1/sqrt(72)
#pragma unroll
    for (int mf = 0; mf < 4; ++mf) {
#pragma unroll
        for (int nf = 0; nf < 4; ++nf) {
            const int row = m0 + wm + mf * 16 + gi;
            const int col = n0 + wn + nf * 8 + tig * 2;
            const float b0 = bias[col], b1 = bias[col + 1];
            float x0 = acc[mf][nf][0] + b0, y0 = acc[mf][nf][1] + b1;
            float x1 = acc[mf][nf][2] + b0, y1 = acc[mf][nf][3] + b1;
            if (MODE == 0) {
                const int which = n0 / ATT;
                const int rem = col - which * ATT;
                const int h = rem / Dd, d = rem - h * Dd;
                const int bb = row >> 10, tok = row & 1023;
                const int bh = bb * Hh + h;
                if (which == 0) {
                    x0 *= qscale; y0 *= qscale; x1 *= qscale; y1 *= qscale;
                    const size_t o0 = ((size_t)bh * Nn + tok) * DP + d;
                    const size_t o1 = o0 + 8 * DP;
                    *reinterpret_cast<__half2*>(&g_qh[o0]) = hilo2(x0, y0, false);
                    *reinterpret_cast<__half2*>(&g_ql[o0]) = hilo2(x0, y0, true);
                    *reinterpret_cast<__half2*>(&g_qh[o1]) = hilo2(x1, y1, false);
                    *reinterpret_cast<__half2*>(&g_ql[o1]) = hilo2(x1, y1, true);
                } else if (which == 1) {
                    const size_t o0 = ((size_t)bh * Nn + tok) * DP + d;
                    const size_t o1 = o0 + 8 * DP;
                    *reinterpret_cast<__half2*>(&g_kh[o0]) = hilo2(x0, y0, false);
                    *reinterpret_cast<__half2*>(&g_kh[o1]) = hilo2(x1, y1, false);
                } else {
                    const size_t b0o = ((size_t)bh * Dd + d) * Nn + tok;
                    const size_t b1o = b0o + Nn;
                    g_vth[b0o]     = __float2half(x0);
                    g_vth[b1o]     = __float2half(y0);
                    g_vth[b0o + 8] = __float2half(x1);
                    g_vth[b1o + 8] = __float2half(y1);
                }
            } else {
                *reinterpret_cast<float2*>(&Cout[(size_t)row * HID + col]) = make_float2(x0, y0);
                *reinterpret_cast<float2*>(&Cout[(size_t)(row + 8) * HID + col]) = make_float2(x1, y1);
            }
        }
    }
}

// ---------------------------------------------------------------------------
// Flash attention: Q hi/lo 2-pass S; P single fp16, single-pass PV.
// ---------------------------------------------------------------------------
namespace {
constexpr int LDSK  = 88;
constexpr int LDSV  = 72;
constexpr int KROWS = 64;
constexpr int QELE  = 128 * LDSK;
constexpr int KELE  = KROWS * LDSK;
constexpr int VELE  = Dd * LDSV;
constexpr int FLASH_SMEM = (2 * QELE + KELE + VELE) * 2;   // 66688 B
}

__global__ __launch_bounds__(256, 2) void k_flash() {
    extern __shared__ __half sm[];
    __half* sQh = sm;
    __half* sQl = sm + QELE;
    __half* sKh = sm + 2 * QELE;
    __half* sVh = sm + 2 * QELE + KELE;

    const int tid  = threadIdx.x;
    const int warp = tid >> 5, lane = tid & 31;
    const int wm  = warp * 16;
    const int gi  = lane >> 2;
    const int tig = lane & 3;
    const int bh = blockIdx.y;
    const int m0 = blockIdx.x * 128;

    const int lane7 = lane & 7;
    const int aRow = lane7 + ((lane & 8) ? 8 : 0);
    const int aK   = (lane & 16) ? 8 : 0;
    const int bRow = lane7 + ((lane & 16) ? 8 : 0);
    const int bK   = (lane & 8) ? 8 : 0;

    const uint32_t uQh = smem_u32(sQh), uQl = smem_u32(sQl);
    const uint32_t uKh = smem_u32(sKh);
    const uint32_t uVh = smem_u32(sVh);

    const __half* __restrict__ Qh = g_qh + (size_t)bh * Nn * DP;
    const __half* __restrict__ Ql = g_ql + (size_t)bh * Nn * DP;
    const __half* __restrict__ Kh = g_kh + (size_t)bh * Nn * DP;
    const __half* __restrict__ Vh = g_vth + (size_t)bh * Dd * Nn;

    auto issueK = [&](int kt) {
        const int nn = kt * KROWS;
#pragma unroll
        for (int c = 0; c < 3; ++c) {
            const int chunk = tid + c * 256;       // KROWS*10 = 640
            if (chunk < KROWS * 10) {
                const int row = chunk / 10;
                const int kc  = chunk - row * 10;
                cp16(smem_u32(sKh + row * LDSK + kc * 8),
                     Kh + (size_t)(nn + row) * DP + kc * 8);
            }
        }
        CP_COMMIT();
    };
    auto issueV = [&](int kt) {
        const int nn = kt * KROWS;
#pragma unroll
        for (int c = 0; c < 3; ++c) {
            const int chunk = tid + c * 256;       // Dd*8 = 576
            if (chunk < Dd * 8) {
                const int row = chunk >> 3;
                const int kc  = chunk & 7;
                cp16(smem_u32(sVh + row * LDSV + kc * 8),
                     Vh + (size_t)row * Nn + nn + kc * 8);
            }
        }
        CP_COMMIT();
    };

    issueK(0);
#pragma unroll
    for (int c = 0; c < 5; ++c) {
        const int chunk = tid + c * 256;
        const int row = chunk / 10;
        const int kc  = chunk - row * 10;
        const int soff = row * LDSK + kc * 8;
        const size_t gq = (size_t)(m0 + row) * DP + kc * 8;
        *reinterpret_cast<uint4*>(&sQh[soff]) = *reinterpret_cast<const uint4*>(&Qh[gq]);
        *reinterpret_cast<uint4*>(&sQl[soff]) = *reinterpret_cast<const uint4*>(&Ql[gq]);
    }

    float m_run0 = -3.4e38f, m_run1 = -3.4e38f;
    float l_run0 = 0.f, l_run1 = 0.f;
    float o[9][4] = {};

    for (int kt = 0; kt < Nn / KROWS; ++kt) {
        CP_WAIT(0);
        __syncthreads();

        issueV(kt);

        // S = Q K^T, 2-pass fp16 (Q hi + Q lo)
        float s[8][4];
#pragma unroll
        for (int nf = 0; nf < 8; ++nf)
            s[nf][0] = s[nf][1] = s[nf][2] = s[nf][3] = 0.f;
#pragma unroll
        for (int ks = 0; ks < DP; ks += 16) {
            uint32_t aH[4], aL[4], b[2][2];
            const uint32_t aoff = ((wm + aRow) * LDSK + ks + aK) * 2;
            ldsm4(aH[0], aH[1], aH[2], aH[3], uQh + aoff);
            ldsm4(aL[0], aL[1], aL[2], aL[3], uQl + aoff);
#pragma unroll
            for (int np = 0; np < 4; ++np) {
                const uint32_t boff = ((np * 16 + bRow) * LDSK + ks + bK) * 2;
                ldsm4(b[0][0], b[0][1], b[1][0], b[1][1], uKh + boff);
                mma16816(s[2 * np],     aH, b[0]);
                mma16816(s[2 * np],     aL, b[0]);
                mma16816(s[2 * np + 1], aH, b[1]);
                mma16816(s[2 * np + 1], aL, b[1]);
            }
        }

        float mt0 = -3.4e38f, mt1 = -3.4e38f;
#pragma unroll
        for (int nf = 0; nf < 8; ++nf) {
            mt0 = fmaxf(mt0, fmaxf(s[nf][0], s[nf][1]));
            mt1 = fmaxf(mt1, fmaxf(s[nf][2], s[nf][3]));
        }
        mt0 = fmaxf(mt0, __shfl_xor_sync(0xffffffffu, mt0, 1));
        mt0 = fmaxf(mt0, __shfl_xor_sync(0xffffffffu, mt0, 2));
        mt1 = fmaxf(mt1, __shfl_xor_sync(0xffffffffu, mt1, 1));
        mt1 = fmaxf(mt1, __shfl_xor_sync(0xffffffffu, mt1, 2));
        const float mn0 = fmaxf(m_run0, mt0);
        const float mn1 = fmaxf(m_run1, mt1);
        const float sc0 = __expf(m_run0 - mn0);
        const float sc1 = __expf(m_run1 - mn1);
        m_run0 = mn0;
        m_run1 = mn1;
#pragma unroll
        for (int nf = 0; nf < 9; ++nf) {
            o[nf][0] *= sc0; o[nf][1] *= sc0;
            o[nf][2] *= sc1; o[nf][3] *= sc1;
        }

        CP_WAIT(0);
        __syncthreads();

        if (kt + 1 < Nn / KROWS) issueK(kt + 1);

        float ps0 = 0.f, ps1 = 0.f;
        // per k16-chunk: exp + pack fp16 + single-pass PV
#pragma unroll
        for (int kc = 0; kc < 4; ++kc) {
            const int nf0 = 2 * kc, nf1 = 2 * kc + 1;
            const float p00 = __expf(s[nf0][0] - mn0), p01 = __expf(s[nf0][1] - mn0);
            const float p02 = __expf(s[nf0][2] - mn1), p03 = __expf(s[nf0][3] - mn1);
            const float p10 = __expf(s[nf1][0] - mn0), p11 = __expf(s[nf1][1] - mn0);
            const float p12 = __expf(s[nf1][2] - mn1), p13 = __expf(s[nf1][3] - mn1);
            ps0 += p00 + p01 + p10 + p11;
            ps1 += p02 + p03 + p12 + p13;
            uint32_t pH[4];
            pH[0] = pack2(p00, p01);
            pH[1] = pack2(p02, p03);
            pH[2] = pack2(p10, p11);
            pH[3] = pack2(p12, p13);

            uint32_t b[9][2];
#pragma unroll
            for (int np = 0; np < 4; ++np) {
                const uint32_t off = ((np * 16 + bRow) * LDSV + kc * 16 + bK) * 2;
                ldsm4(b[2 * np][0], b[2 * np][1], b[2 * np + 1][0], b[2 * np + 1][1], uVh + off);
            }
            {
                const uint32_t off = ((64 + lane7) * LDSV + kc * 16 + bK) * 2;
                ldsm2(b[8][0], b[8][1], uVh + off);
            }
#pragma unroll
            for (int nf = 0; nf < 9; ++nf)
                mma16816(o[nf], pH, b[nf]);
        }
        ps0 += __shfl_xor_sync(0xffffffffu, ps0, 1);
        ps0 += __shfl_xor_sync(0xffffffffu, ps0, 2);
        ps1 += __shfl_xor_sync(0xffffffffu, ps1, 1);
        ps1 += __shfl_xor_sync(0xffffffffu, ps1, 2);
        l_run0 = l_run0 * sc0 + ps0;
        l_run1 = l_run1 * sc1 + ps1;
    }

    const float inv0 = 1.0f / l_run0;
    const float inv1 = 1.0f / l_run1;
    const int b = bh >> 4;
    const int h = bh & 15;
    const int tok0 = m0 + wm + gi;
#pragma unroll
    for (int nf = 0; nf < 9; ++nf) {
        const int col = nf * 8 + tig * 2;
        const size_t o0 = ((size_t)(b * Nn + tok0)) * HID + h * Dd + col;
        const size_t o1 = ((size_t)(b * Nn + tok0 + 8)) * HID + h * Dd + col;
        *reinterpret_cast<__half2*>(&g_oa[o0]) =
            __halves2half2(__float2half(o[nf][0] * inv0), __float2half(o[nf][1] * inv0));
        *reinterpret_cast<__half2*>(&g_oa[o1]) =
            __halves2half2(__float2half(o[nf][2] * inv1), __float2half(o[nf][3] * inv1));
    }
}

// ---------------------------------------------------------------------------
extern "C" void kernel_launch(void* const* d_in, const int* in_sizes, int n_in,
                              void* d_out, int out_size) {
    const float* x     = (const float*)d_in[0];
    const float* w_qkv = (const float*)d_in[1];
    const float* b_qkv = (const float*)d_in[2];
    const float* w_out = (const float*)d_in[3];
    const float* b_out = (const float*)d_in[4];
    float* out = (float*)d_out;

    cudaFuncSetAttribute(k_flash, cudaFuncAttributeMaxDynamicSharedMemorySize, FLASH_SMEM);
    cudaFuncSetAttribute(k_gemm<0>, cudaFuncAttributeMaxDynamicSharedMemorySize, GEMM_SMEM);
    cudaFuncSetAttribute(k_gemm<1>, cudaFuncAttributeMaxDynamicSharedMemorySize, GEMM_SMEM);

    const int n4 = MTOK * HID / 4;

    // prep
    k_split<<<(n4 + 255) / 256, 256>>>(x);
    k_tsplit<QKVN, 0><<<dim3(QKVN / 32, HID / 32), dim3(32, 8)>>>(w_qkv);
    k_tsplit<HID, 1><<<dim3(HID / 32, HID / 32), dim3(32, 8)>>>(w_out);

    // 1. QKV projection -> Q(scaled) hi/lo (padded), K fp16, V^T fp16
    k_gemm<0><<<dim3(QKVN / 128, MTOK / 128), 256, GEMM_SMEM>>>(b_qkv, nullptr);

    // 2. fused flash attention -> g_oa fp16
    k_flash<<<dim3(Nn / 128, BHEAD), 256, FLASH_SMEM>>>();

    // 3. output projection
    k_gemm<1><<<dim3(HID / 128, MTOK / 128), 256, GEMM_SMEM>>>(b_out, out);
}

// round 15
// speedup vs baseline: 2.4861x; 1.1085x over previous
#include <cuda_runtime.h>
#include <cuda_fp16.h>
#include <cstdint>

// ---------------------------------------------------------------------------
// Attention_21474836480706: B=4, N=1024, H=16, D=72, HID=1152 (fp32)
// R15: flash S single-pass (Q plain fp16 -> QK^T one MMA pass); all prep
// fused into one region-dispatched kernel. Calibrated error ~6.0e-4 < 1e-3.
// ---------------------------------------------------------------------------

namespace {
constexpr int Bb    = 4;
constexpr int Nn    = 1024;
constexpr int Hh    = 16;
constexpr int Dd    = 72;
constexpr int DP    = 80;
constexpr int HID   = 1152;
constexpr int ATT   = Hh * Dd;        // 1152
constexpr int MTOK  = Bb * Nn;        // 4096
constexpr int QKVN  = 3 * ATT;        // 3456
constexpr int BHEAD = Bb * Hh;        // 64
}

// ------------------------------ scratch ------------------------------------
__device__ __align__(16) __half g_qh[(size_t)BHEAD * Nn * DP];   // Q fp16 (pre-scaled)
__device__ __align__(16) __half g_kh[(size_t)BHEAD * Nn * DP];   // K fp16
__device__ __align__(16) __half g_vth[(size_t)BHEAD * Dd * Nn];  // V^T fp16

__device__ __align__(16) __half g_xa[(size_t)MTOK * HID];        // x fp16
__device__ __align__(16) __half g_oa[(size_t)MTOK * HID];        // attn out fp16
__device__ __align__(16) __half g_wqkvt[(size_t)QKVN * HID];     // W_qkv^T fp16
__device__ __align__(16) __half g_wot[(size_t)HID * HID];        // W_out^T fp16

// --------------------------- helpers ---------------------------------------
__device__ __forceinline__ uint32_t smem_u32(const void* p) {
    uint32_t a;
    asm("{ .reg .u64 t; cvta.to.shared.u64 t, %1; cvt.u32.u64 %0, t; }" : "=r"(a) : "l"(p));
    return a;
}
__device__ __forceinline__ void cp16(uint32_t s, const void* g) {
    asm volatile("cp.async.cg.shared.global [%0], [%1], 16;" :: "r"(s), "l"(g));
}
#define CP_COMMIT() asm volatile("cp.async.commit_group;" ::: "memory")
#define CP_WAIT(n)  asm volatile("cp.async.wait_group %0;" :: "n"(n) : "memory")

__device__ __forceinline__ void ldsm4(uint32_t& r0, uint32_t& r1, uint32_t& r2, uint32_t& r3,
                                      uint32_t a) {
    asm volatile("ldmatrix.sync.aligned.m8n8.x4.shared.b16 {%0,%1,%2,%3}, [%4];"
                 : "=r"(r0), "=r"(r1), "=r"(r2), "=r"(r3) : "r"(a));
}
__device__ __forceinline__ void ldsm2(uint32_t& r0, uint32_t& r1, uint32_t a) {
    asm volatile("ldmatrix.sync.aligned.m8n8.x2.shared.b16 {%0,%1}, [%2];"
                 : "=r"(r0), "=r"(r1) : "r"(a));
}
__device__ __forceinline__ void mma16816(float* d, const uint32_t* a, const uint32_t* b) {
    asm volatile(
        "mma.sync.aligned.m16n8k16.row.col.f32.f16.f16.f32 "
        "{%0,%1,%2,%3}, {%4,%5,%6,%7}, {%8,%9}, {%0,%1,%2,%3};"
        : "+f"(d[0]), "+f"(d[1]), "+f"(d[2]), "+f"(d[3])
        : "r"(a[0]), "r"(a[1]), "r"(a[2]), "r"(a[3]), "r"(b[0]), "r"(b[1]));
}
__device__ __forceinline__ uint32_t pack2(float a, float b) {
    __half2 h2 = __halves2half2(__float2half(a), __float2half(b));
    return *reinterpret_cast<uint32_t*>(&h2);
}

// ---------------------------------------------------------------------------
// Fused prep: region-dispatched on blockIdx.x.
//   [0, NB_X):          x fp32 -> fp16 convert (+ Q/K pad zeroing)
//   [NB_X, +NB_WQ):     W_qkv transpose -> g_wqkvt
//   [.., +NB_WO):       W_out transpose -> g_wot
// ---------------------------------------------------------------------------
namespace {
constexpr int NB_X  = MTOK * HID / 4 / 256;        // 4608
constexpr int NB_WQ = (QKVN / 32) * (HID / 32);    // 3888
constexpr int NB_WO = (HID / 32) * (HID / 32);     // 1296
constexpr int NB_PREP = NB_X + NB_WQ + NB_WO;      // 9792
}

__global__ __launch_bounds__(256) void k_prep(const float* __restrict__ x,
                                              const float* __restrict__ w_qkv,
                                              const float* __restrict__ w_out) {
    __shared__ float t[32][33];
    const int bid = blockIdx.x;
    const int tid = threadIdx.x;

    if (bid < NB_X) {
        const int i = bid * 256 + tid;
        float4 v = reinterpret_cast<const float4*>(x)[i];
        reinterpret_cast<__half2*>(g_xa)[2 * i] =
            __halves2half2(__float2half(v.x), __float2half(v.y));
        reinterpret_cast<__half2*>(g_xa)[2 * i + 1] =
            __halves2half2(__float2half(v.z), __float2half(v.w));
        if (i < BHEAD * Nn) {   // zero D-pad of Q + K
            const size_t o = (size_t)i * DP + Dd;
            const uint4 z = make_uint4(0, 0, 0, 0);
            *reinterpret_cast<uint4*>(&g_qh[o]) = z;
            *reinterpret_cast<uint4*>(&g_kh[o]) = z;
        }
        return;
    }

    // weight transpose regions
    const bool isWQ = (bid < NB_X + NB_WQ);
    const int  b2   = isWQ ? (bid - NB_X) : (bid - NB_X - NB_WQ);
    const int  NC   = isWQ ? QKVN : HID;
    const int  nTil = NC / 32;
    const int  n0 = (b2 % nTil) * 32;
    const int  k0 = (b2 / nTil) * 32;
    const float* W = isWQ ? w_qkv : w_out;
    __half* Wt = isWQ ? g_wqkvt : g_wot;

    const int tx = tid & 31, ty = tid >> 5;   // (32, 8)
#pragma unroll
    for (int i = 0; i < 4; ++i)
        t[ty * 4 + i][tx] = W[(size_t)(k0 + ty * 4 + i) * NC + n0 + tx];
    __syncthreads();
#pragma unroll
    for (int i = 0; i < 4; ++i)
        Wt[(size_t)(n0 + ty * 4 + i) * HID + k0 + tx] = __float2half(t[tx][ty * 4 + i]);
}

// ---------------------------------------------------------------------------
// HMMA GEMM (projections): single-pass fp16, GBK=64, 2-stage, 2 CTAs/SM.
// ---------------------------------------------------------------------------
namespace {
constexpr int GBM = 128, GBK = 64, GLDS = 72;
constexpr int GTILE = GBM * GLDS;
constexpr int GSTAGE = 2 * GTILE;
constexpr int GEMM_SMEM = 2 * GSTAGE * 2;         // 73728 B
}

template <int MODE>
__global__ __launch_bounds__(256, 2) void k_gemm(const float* __restrict__ bias,
                                                 float* __restrict__ Cout) {
    extern __shared__ __half gsm[];

    const int tid  = threadIdx.x;
    const int warp = tid >> 5, lane = tid & 31;
    const int wm = (warp >> 2) * 64;
    const int wn = (warp & 3) * 32;
    const int gi  = lane >> 2;
    const int tig = lane & 3;
    const int m0 = blockIdx.y * GBM;
    const int n0 = blockIdx.x * GBM;

    const int lane7 = lane & 7;
    const int aRow = lane7 + ((lane & 8) ? 8 : 0);
    const int aK   = (lane & 16) ? 8 : 0;
    const int bRow = lane7 + ((lane & 16) ? 8 : 0);
    const int bK   = (lane & 8) ? 8 : 0;

    const __half* __restrict__ Ah = MODE ? g_oa : g_xa;
    const __half* __restrict__ Bh = MODE ? g_wot : g_wqkvt;

    auto issue_tile = [&](int kt, int stage) {
        __half* base = gsm + stage * GSTAGE;
        const int kk = kt * GBK;
#pragma unroll
        for (int c = 0; c < 4; ++c) {
            const int chunk = tid + c * 256;
            const int row = chunk >> 3;
            const int kc  = chunk & 7;
            const uint32_t soff = smem_u32(base + row * GLDS + kc * 8);
            cp16(soff,             Ah + (size_t)(m0 + row) * HID + kk + kc * 8);
            cp16(soff + GTILE * 2, Bh + (size_t)(n0 + row) * HID + kk + kc * 8);
        }
        CP_COMMIT();
    };

    float acc[4][4][4] = {};
    constexpr int NT = HID / GBK;   // 18

    issue_tile(0, 0);

    for (int t = 0; t < NT; ++t) {
        if (t + 1 < NT) {
            issue_tile(t + 1, (t + 1) & 1);
            CP_WAIT(1);
        } else {
            CP_WAIT(0);
        }
        __syncthreads();

        const uint32_t uAh = smem_u32(gsm + (t & 1) * GSTAGE);
        const uint32_t uBh = uAh + GTILE * 2;

#pragma unroll
        for (int ks = 0; ks < GBK; ks += 16) {
            uint32_t b[4][2];
#pragma unroll
            for (int np = 0; np < 2; ++np) {
                const uint32_t off = ((wn + np * 16 + bRow) * GLDS + ks + bK) * 2;
                ldsm4(b[2 * np][0], b[2 * np][1], b[2 * np + 1][0], b[2 * np + 1][1],
                      uBh + off);
            }
#pragma unroll
            for (int mf = 0; mf < 4; ++mf) {
                uint32_t ah[4];
                const uint32_t off = ((wm + mf * 16 + aRow) * GLDS + ks + aK) * 2;
                ldsm4(ah[0], ah[1], ah[2], ah[3], uAh + off);
#pragma unroll
                for (int nf = 0; nf < 4; ++nf)
                    mma16816(acc[mf][nf], ah, b[nf]);
            }
        }
        __syncthreads();
    }

    const float qscale = 0.11785113019775793f;  // 1/sqrt(72)
#pragma unroll
    for (int mf = 0; mf < 4; ++mf) {
#pragma unroll
        for (int nf = 0; nf < 4; ++nf) {
            const int row = m0 + wm + mf * 16 + gi;
            const int col = n0 + wn + nf * 8 + tig * 2;
            const float b0 = bias[col], b1 = bias[col + 1];
            float x0 = acc[mf][nf][0] + b0, y0 = acc[mf][nf][1] + b1;
            float x1 = acc[mf][nf][2] + b0, y1 = acc[mf][nf][3] + b1;
            if (MODE == 0) {
                const int which = n0 / ATT;
                const int rem = col - which * ATT;
                const int h = rem / Dd, d = rem - h * Dd;
                const int bb = row >> 10, tok = row & 1023;
                const int bh = bb * Hh + h;
                if (which < 2) {
                    if (which == 0) { x0 *= qscale; y0 *= qscale; x1 *= qscale; y1 *= qscale; }
                    __half* dst = which ? g_kh : g_qh;
                    const size_t o0 = ((size_t)bh * Nn + tok) * DP + d;
                    const size_t o1 = o0 + 8 * DP;
                    *reinterpret_cast<__half2*>(&dst[o0]) =
                        __halves2half2(__float2half(x0), __float2half(y0));
                    *reinterpret_cast<__half2*>(&dst[o1]) =
                        __halves2half2(__float2half(x1), __float2half(y1));
                } else {
                    const size_t b0o = ((size_t)bh * Dd + d) * Nn + tok;
                    const size_t b1o = b0o + Nn;
                    g_vth[b0o]     = __float2half(x0);
                    g_vth[b1o]     = __float2half(y0);
                    g_vth[b0o + 8] = __float2half(x1);
                    g_vth[b1o + 8] = __float2half(y1);
                }
            } else {
                *reinterpret_cast<float2*>(&Cout[(size_t)row * HID + col]) = make_float2(x0, y0);
                *reinterpret_cast<float2*>(&Cout[(size_t)(row + 8) * HID + col]) = make_float2(x1, y1);
            }
        }
    }
}

// ---------------------------------------------------------------------------
// Flash attention: single-pass fp16 throughout (Q, K, P, V plain fp16).
// ---------------------------------------------------------------------------
namespace {
constexpr int LDSK  = 88;
constexpr int LDSV  = 72;
constexpr int KROWS = 64;
constexpr int QELE  = 128 * LDSK;
constexpr int KELE  = KROWS * LDSK;
constexpr int VELE  = Dd * LDSV;
constexpr int FLASH_SMEM = (QELE + KELE + VELE) * 2;   // 44160 B
}

__global__ __launch_bounds__(256, 2) void k_flash() {
    extern __shared__ __half sm[];
    __half* sQh = sm;
    __half* sKh = sm + QELE;
    __half* sVh = sm + QELE + KELE;

    const int tid  = threadIdx.x;
    const int warp = tid >> 5, lane = tid & 31;
    const int wm  = warp * 16;
    const int gi  = lane >> 2;
    const int tig = lane & 3;
    const int bh = blockIdx.y;
    const int m0 = blockIdx.x * 128;

    const int lane7 = lane & 7;
    const int aRow = lane7 + ((lane & 8) ? 8 : 0);
    const int aK   = (lane & 16) ? 8 : 0;
    const int bRow = lane7 + ((lane & 16) ? 8 : 0);
    const int bK   = (lane & 8) ? 8 : 0;

    const uint32_t uQh = smem_u32(sQh);
    const uint32_t uKh = smem_u32(sKh);
    const uint32_t uVh = smem_u32(sVh);

    const __half* __restrict__ Qh = g_qh + (size_t)bh * Nn * DP;
    const __half* __restrict__ Kh = g_kh + (size_t)bh * Nn * DP;
    const __half* __restrict__ Vh = g_vth + (size_t)bh * Dd * Nn;

    auto issueK = [&](int kt) {
        const int nn = kt * KROWS;
#pragma unroll
        for (int c = 0; c < 3; ++c) {
            const int chunk = tid + c * 256;       // KROWS*10 = 640
            if (chunk < KROWS * 10) {
                const int row = chunk / 10;
                const int kc  = chunk - row * 10;
                cp16(smem_u32(sKh + row * LDSK + kc * 8),
                     Kh + (size_t)(nn + row) * DP + kc * 8);
            }
        }
        CP_COMMIT();
    };
    auto issueV = [&](int kt) {
        const int nn = kt * KROWS;
#pragma unroll
        for (int c = 0; c < 3; ++c) {
            const int chunk = tid + c * 256;       // Dd*8 = 576
            if (chunk < Dd * 8) {
                const int row = chunk >> 3;
                const int kc  = chunk & 7;
                cp16(smem_u32(sVh + row * LDSV + kc * 8),
                     Vh + (size_t)row * Nn + nn + kc * 8);
            }
        }
        CP_COMMIT();
    };

    issueK(0);
#pragma unroll
    for (int c = 0; c < 5; ++c) {
        const int chunk = tid + c * 256;
        const int row = chunk / 10;
        const int kc  = chunk - row * 10;
        const size_t gq = (size_t)(m0 + row) * DP + kc * 8;
        *reinterpret_cast<uint4*>(&sQh[row * LDSK + kc * 8]) =
            *reinterpret_cast<const uint4*>(&Qh[gq]);
    }

    float m_run0 = -3.4e38f, m_run1 = -3.4e38f;
    float l_run0 = 0.f, l_run1 = 0.f;
    float o[9][4] = {};

    for (int kt = 0; kt < Nn / KROWS; ++kt) {
        CP_WAIT(0);
        __syncthreads();

        issueV(kt);

        // S = Q K^T, single-pass fp16
        float s[8][4];
#pragma unroll
        for (int nf = 0; nf < 8; ++nf)
            s[nf][0] = s[nf][1] = s[nf][2] = s[nf][3] = 0.f;
#pragma unroll
        for (int ks = 0; ks < DP; ks += 16) {
            uint32_t aH[4], b[2][2];
            const uint32_t aoff = ((wm + aRow) * LDSK + ks + aK) * 2;
            ldsm4(aH[0], aH[1], aH[2], aH[3], uQh + aoff);
#pragma unroll
            for (int np = 0; np < 4; ++np) {
                const uint32_t boff = ((np * 16 + bRow) * LDSK + ks + bK) * 2;
                ldsm4(b[0][0], b[0][1], b[1][0], b[1][1], uKh + boff);
                mma16816(s[2 * np],     aH, b[0]);
                mma16816(s[2 * np + 1], aH, b[1]);
            }
        }

        float mt0 = -3.4e38f, mt1 = -3.4e38f;
#pragma unroll
        for (int nf = 0; nf < 8; ++nf) {
            mt0 = fmaxf(mt0, fmaxf(s[nf][0], s[nf][1]));
            mt1 = fmaxf(mt1, fmaxf(s[nf][2], s[nf][3]));
        }
        mt0 = fmaxf(mt0, __shfl_xor_sync(0xffffffffu, mt0, 1));
        mt0 = fmaxf(mt0, __shfl_xor_sync(0xffffffffu, mt0, 2));
        mt1 = fmaxf(mt1, __shfl_xor_sync(0xffffffffu, mt1, 1));
        mt1 = fmaxf(mt1, __shfl_xor_sync(0xffffffffu, mt1, 2));
        const float mn0 = fmaxf(m_run0, mt0);
        const float mn1 = fmaxf(m_run1, mt1);
        const float sc0 = __expf(m_run0 - mn0);
        const float sc1 = __expf(m_run1 - mn1);
        m_run0 = mn0;
        m_run1 = mn1;
#pragma unroll
        for (int nf = 0; nf < 9; ++nf) {
            o[nf][0] *= sc0; o[nf][1] *= sc0;
            o[nf][2] *= sc1; o[nf][3] *= sc1;
        }

        CP_WAIT(0);
        __syncthreads();

        if (kt + 1 < Nn / KROWS) issueK(kt + 1);

        float ps0 = 0.f, ps1 = 0.f;
#pragma unroll
        for (int kc = 0; kc < 4; ++kc) {
            const int nf0 = 2 * kc, nf1 = 2 * kc + 1;
            const float p00 = __expf(s[nf0][0] - mn0), p01 = __expf(s[nf0][1] - mn0);
            const float p02 = __expf(s[nf0][2] - mn1), p03 = __expf(s[nf0][3] - mn1);
            const float p10 = __expf(s[nf1][0] - mn0), p11 = __expf(s[nf1][1] - mn0);
            const float p12 = __expf(s[nf1][2] - mn1), p13 = __expf(s[nf1][3] - mn1);
            ps0 += p00 + p01 + p10 + p11;
            ps1 += p02 + p03 + p12 + p13;
            uint32_t pH[4];
            pH[0] = pack2(p00, p01);
            pH[1] = pack2(p02, p03);
            pH[2] = pack2(p10, p11);
            pH[3] = pack2(p12, p13);

            uint32_t b[9][2];
#pragma unroll
            for (int np = 0; np < 4; ++np) {
                const uint32_t off = ((np * 16 + bRow) * LDSV + kc * 16 + bK) * 2;
                ldsm4(b[2 * np][0], b[2 * np][1], b[2 * np + 1][0], b[2 * np + 1][1], uVh + off);
            }
            {
                const uint32_t off = ((64 + lane7) * LDSV + kc * 16 + bK) * 2;
                ldsm2(b[8][0], b[8][1], uVh + off);
            }
#pragma unroll
            for (int nf = 0; nf < 9; ++nf)
                mma16816(o[nf], pH, b[nf]);
        }
        ps0 += __shfl_xor_sync(0xffffffffu, ps0, 1);
        ps0 += __shfl_xor_sync(0xffffffffu, ps0, 2);
        ps1 += __shfl_xor_sync(0xffffffffu, ps1, 1);
        ps1 += __shfl_xor_sync(0xffffffffu, ps1, 2);
        l_run0 = l_run0 * sc0 + ps0;
        l_run1 = l_run1 * sc1 + ps1;
    }

    const float inv0 = 1.0f / l_run0;
    const float inv1 = 1.0f / l_run1;
    const int b = bh >> 4;
    const int h = bh & 15;
    const int tok0 = m0 + wm + gi;
#pragma unroll
    for (int nf = 0; nf < 9; ++nf) {
        const int col = nf * 8 + tig * 2;
        const size_t o0 = ((size_t)(b * Nn + tok0)) * HID + h * Dd + col;
        const size_t o1 = ((size_t)(b * Nn + tok0 + 8)) * HID + h * Dd + col;
        *reinterpret_cast<__half2*>(&g_oa[o0]) =
            __halves2half2(__float2half(o[nf][0] * inv0), __float2half(o[nf][1] * inv0));
        *reinterpret_cast<__half2*>(&g_oa[o1]) =
            __halves2half2(__float2half(o[nf][2] * inv1), __float2half(o[nf][3] * inv1));
    }
}

// ---------------------------------------------------------------------------
extern "C" void kernel_launch(void* const* d_in, const int* in_sizes, int n_in,
                              void* d_out, int out_size) {
    const float* x     = (const float*)d_in[0];
    const float* w_qkv = (const float*)d_in[1];
    const float* b_qkv = (const float*)d_in[2];
    const float* w_out = (const float*)d_in[3];
    const float* b_out = (const float*)d_in[4];
    float* out = (float*)d_out;

    cudaFuncSetAttribute(k_flash, cudaFuncAttributeMaxDynamicSharedMemorySize, FLASH_SMEM);
    cudaFuncSetAttribute(k_gemm<0>, cudaFuncAttributeMaxDynamicSharedMemorySize, GEMM_SMEM);
    cudaFuncSetAttribute(k_gemm<1>, cudaFuncAttributeMaxDynamicSharedMemorySize, GEMM_SMEM);

    // fused prep (x convert + pad zero + both weight transposes)
    k_prep<<<NB_PREP, 256>>>(x, w_qkv, w_out);

    // 1. QKV projection -> Q(scaled)/K fp16 (padded), V^T fp16
    k_gemm<0><<<dim3(QKVN / 128, MTOK / 128), 256, GEMM_SMEM>>>(b_qkv, nullptr);

    // 2. fused flash attention -> g_oa fp16
    k_flash<<<dim3(Nn / 128, BHEAD), 256, FLASH_SMEM>>>();

    // 3. output projection
    k_gemm<1><<<dim3(HID / 128, MTOK / 128), 256, GEMM_SMEM>>>(b_out, out);
}